// round 1
// baseline (speedup 1.0000x reference)
#include <cuda_runtime.h>
#include <math.h>

#define S_DIM 4096
#define E_DIM 2048
#define H_NUM 16
#define D_HEAD 128
#define T_NUM 32

// Scratch (alloc-free rule: __device__ globals)
__device__ float g_q[H_NUM * S_DIM * D_HEAD];
__device__ float g_k[H_NUM * S_DIM * D_HEAD];
__device__ float g_v[H_NUM * S_DIM * D_HEAD];
__device__ float g_att[S_DIM * E_DIM];

// ---------------------------------------------------------------------------
// 128x128x8 register-blocked SGEMM: C[M,N] = A[M,K] @ B[K,N]
// M=4096, N=2048, K=2048 (all multiples of tile sizes, no bounds checks).
// mode 0: plain row-major store to out[M,N]
// mode 1: head-major store out[h][s][d]  (h = n0/128, d = col-in-head)
// mode 2: head-major store with RoPE rotation fused in epilogue
// Thread microtile: rows {ty*4..+3, 64+ty*4..+3}, cols {tx*4..+3, 64+tx*4..+3}
// -> cols d and d+64 live in the SAME thread, so rotate_half pairs are local.
// ---------------------------------------------------------------------------
__global__ __launch_bounds__(256, 1)
void gemm128_kernel(const float* __restrict__ A, const float* __restrict__ B,
                    float* __restrict__ out, const float* __restrict__ rope,
                    int mode)
{
    __shared__ float As[8][128];
    __shared__ float Bs[8][128];
    const int N = E_DIM, K = E_DIM;

    const int bx = blockIdx.x;           // N / 128
    const int by = blockIdx.y;           // M / 128
    const int tid = threadIdx.x;
    const int tx = tid & 15;
    const int ty = tid >> 4;
    const int m0 = by * 128;
    const int n0 = bx * 128;

    float c[8][8];
#pragma unroll
    for (int i = 0; i < 8; i++)
#pragma unroll
        for (int j = 0; j < 8; j++) c[i][j] = 0.0f;

    // A tile loader: 128 rows x 8 cols, one float4 per thread
    const int arow = tid >> 1;           // 0..127
    const int acol = (tid & 1) * 4;      // 0 or 4
    const float* Aptr = A + (m0 + arow) * K + acol;
    // B tile loader: 8 rows x 128 cols, one float4 per thread (coalesced)
    const int brow = tid >> 5;           // 0..7
    const int bcol = (tid & 31) * 4;     // 0..124
    const float* Bptr = B + brow * N + n0 + bcol;

    for (int kb = 0; kb < K; kb += 8) {
        float4 av = *(const float4*)(Aptr + kb);
        As[acol + 0][arow] = av.x;
        As[acol + 1][arow] = av.y;
        As[acol + 2][arow] = av.z;
        As[acol + 3][arow] = av.w;
        *(float4*)&Bs[brow][bcol] = *(const float4*)(Bptr + kb * N);
        __syncthreads();

#pragma unroll
        for (int kk = 0; kk < 8; kk++) {
            float a[8], b[8];
#pragma unroll
            for (int i = 0; i < 4; i++) {
                a[i]     = As[kk][ty * 4 + i];
                a[4 + i] = As[kk][64 + ty * 4 + i];
            }
#pragma unroll
            for (int j = 0; j < 4; j++) {
                b[j]     = Bs[kk][tx * 4 + j];
                b[4 + j] = Bs[kk][64 + tx * 4 + j];
            }
#pragma unroll
            for (int i = 0; i < 8; i++)
#pragma unroll
                for (int j = 0; j < 8; j++)
                    c[i][j] = fmaf(a[i], b[j], c[i][j]);
        }
        __syncthreads();
    }

    if (mode == 0) {
#pragma unroll
        for (int i = 0; i < 8; i++) {
            int r = (i < 4) ? (ty * 4 + i) : (64 + ty * 4 + (i - 4));
            float* orow = out + (m0 + r) * N + n0;
#pragma unroll
            for (int j = 0; j < 4; j++) {
                orow[tx * 4 + j]      = c[i][j];
                orow[64 + tx * 4 + j] = c[i][4 + j];
            }
        }
    } else {
        const int h = n0 >> 7;  // one head per 128-wide N tile
        float* hout = out + h * (S_DIM * D_HEAD);
#pragma unroll
        for (int i = 0; i < 8; i++) {
            int r = (i < 4) ? (ty * 4 + i) : (64 + ty * 4 + (i - 4));
            int s = m0 + r;
            float* orow = hout + s * D_HEAD;
#pragma unroll
            for (int j = 0; j < 4; j++) {
                int dlo = tx * 4 + j;       // 0..63
                float lo = c[i][j];
                float hi = c[i][4 + j];     // column dlo + 64
                if (mode == 2) {
                    float ang = rope[s * (D_HEAD / 2) + dlo];
                    float sn, cs;
                    __sincosf(ang, &sn, &cs);
                    float nlo = lo * cs - hi * sn;   // x*cos + rot(x)*sin, d<64
                    float nhi = hi * cs + lo * sn;   // d>=64 half
                    lo = nlo;
                    hi = nhi;
                }
                orow[dlo]      = lo;
                orow[64 + dlo] = hi;
            }
        }
    }
}

// ---------------------------------------------------------------------------
// Block-sparse attention, one CTA per (q-tile t, head h).
// smem: Qs = Q^T [128d][129], KP = K^T then P^T [128][129], Vs [128k][128d].
// Online softmax across the 9 selected key tiles (8 anchors + local diag).
// ---------------------------------------------------------------------------
#define NEG_BIG (-1e10f)

__global__ __launch_bounds__(256, 1)
void attn_kernel(const int* __restrict__ anchors, int kanch)
{
    extern __shared__ float sm[];
    float (*Qs)[129] = (float(*)[129])sm;
    float (*KP)[129] = (float(*)[129])(sm + 128 * 129);
    float (*Vs)[128] = (float(*)[128])(sm + 2 * 128 * 129);

    const int t = blockIdx.x;
    const int h = blockIdx.y;
    const int tid = threadIdx.x;
    const int tx = tid & 15;
    const int ty = tid >> 4;
    const float sm_scale = 0.088388347648318447f;  // 1/sqrt(128)

    // Load Q^T once
    const float* qg = g_q + (h * S_DIM + t * 128) * D_HEAD;
    for (int i = tid; i < 128 * 32; i += 256) {
        int q = i >> 5;
        int dg = (i & 31) * 4;
        float4 v = *(const float4*)(qg + q * 128 + dg);
        Qs[dg + 0][q] = v.x;
        Qs[dg + 1][q] = v.y;
        Qs[dg + 2][q] = v.z;
        Qs[dg + 3][q] = v.w;
    }

    int r[8], cc[8];
#pragma unroll
    for (int i = 0; i < 4; i++) {
        r[i] = ty * 4 + i;
        r[4 + i] = 64 + ty * 4 + i;
        cc[i] = tx * 4 + i;
        cc[4 + i] = 64 + tx * 4 + i;
    }

    float O[8][8];
    float mrow[8], lrow[8];
#pragma unroll
    for (int i = 0; i < 8; i++) {
        mrow[i] = -1e30f;
        lrow[i] = 0.0f;
#pragma unroll
        for (int j = 0; j < 8; j++) O[i][j] = 0.0f;
    }

    for (int it = 0; it <= kanch; it++) {
        int tile = (it < kanch) ? anchors[(h * T_NUM + t) * kanch + it] : t;

        __syncthreads();  // previous PV done reading KP/Vs
        const float* kg = g_k + (h * S_DIM + tile * 128) * D_HEAD;
        const float* vg = g_v + (h * S_DIM + tile * 128) * D_HEAD;
        for (int i = tid; i < 128 * 32; i += 256) {
            int kq = i >> 5;
            int dg = (i & 31) * 4;
            float4 kv = *(const float4*)(kg + kq * 128 + dg);
            KP[dg + 0][kq] = kv.x;
            KP[dg + 1][kq] = kv.y;
            KP[dg + 2][kq] = kv.z;
            KP[dg + 3][kq] = kv.w;
            *(float4*)&Vs[kq][dg] = *(const float4*)(vg + kq * 128 + dg);
        }
        __syncthreads();

        // S = Q @ K^T  (inner over d)
        float sreg[8][8];
#pragma unroll
        for (int i = 0; i < 8; i++)
#pragma unroll
            for (int j = 0; j < 8; j++) sreg[i][j] = 0.0f;

        for (int d = 0; d < 128; d++) {
            float a[8], b[8];
#pragma unroll
            for (int i = 0; i < 8; i++) a[i] = Qs[d][r[i]];
#pragma unroll
            for (int j = 0; j < 8; j++) b[j] = KP[d][cc[j]];
#pragma unroll
            for (int i = 0; i < 8; i++)
#pragma unroll
                for (int j = 0; j < 8; j++)
                    sreg[i][j] = fmaf(a[i], b[j], sreg[i][j]);
        }

        // scale + causal mask (future gathered keys -> NEG)
        const int kbase = tile * 128;
        const int qbase = t * 128;
#pragma unroll
        for (int i = 0; i < 8; i++) {
            int qpos = qbase + r[i];
#pragma unroll
            for (int j = 0; j < 8; j++) {
                float v = sreg[i][j] * sm_scale;
                if (kbase + cc[j] > qpos) v = NEG_BIG;
                sreg[i][j] = v;
            }
        }

        // online softmax; rows of a query are spread across the 16-lane tx group
#pragma unroll
        for (int i = 0; i < 8; i++) {
            float mx = sreg[i][0];
#pragma unroll
            for (int j = 1; j < 8; j++) mx = fmaxf(mx, sreg[i][j]);
#pragma unroll
            for (int off = 1; off < 16; off <<= 1)
                mx = fmaxf(mx, __shfl_xor_sync(0xffffffffu, mx, off));
            float mnew = fmaxf(mrow[i], mx);
            float fac = __expf(mrow[i] - mnew);
            float ls = 0.0f;
#pragma unroll
            for (int j = 0; j < 8; j++) {
                sreg[i][j] = __expf(sreg[i][j] - mnew);
                ls += sreg[i][j];
            }
#pragma unroll
            for (int off = 1; off < 16; off <<= 1)
                ls += __shfl_xor_sync(0xffffffffu, ls, off);
            lrow[i] = lrow[i] * fac + ls;
            mrow[i] = mnew;
#pragma unroll
            for (int j = 0; j < 8; j++) O[i][j] *= fac;
        }

        __syncthreads();  // everyone done reading KP as K^T
        // P^T into KP
#pragma unroll
        for (int i = 0; i < 8; i++)
#pragma unroll
            for (int j = 0; j < 8; j++) KP[cc[j]][r[i]] = sreg[i][j];
        __syncthreads();

        // O += P @ V  (inner over k; KP holds P^T[k][q], Vs holds V[k][d])
        for (int kk = 0; kk < 128; kk++) {
            float a[8], b[8];
#pragma unroll
            for (int i = 0; i < 8; i++) a[i] = KP[kk][r[i]];
#pragma unroll
            for (int j = 0; j < 8; j++) b[j] = Vs[kk][cc[j]];
#pragma unroll
            for (int i = 0; i < 8; i++)
#pragma unroll
                for (int j = 0; j < 8; j++)
                    O[i][j] = fmaf(a[i], b[j], O[i][j]);
        }
    }

    // normalize + store to [S, H*D] for the output projection
    float* og = g_att + (t * 128) * E_DIM + h * D_HEAD;
#pragma unroll
    for (int i = 0; i < 8; i++) {
        float inv = 1.0f / lrow[i];
        float* orow = og + r[i] * E_DIM;
#pragma unroll
        for (int j = 0; j < 8; j++) orow[cc[j]] = O[i][j] * inv;
    }
}

// ---------------------------------------------------------------------------
extern "C" void kernel_launch(void* const* d_in, const int* in_sizes, int n_in,
                              void* d_out, int out_size)
{
    const float* x    = (const float*)d_in[0];
    const float* wq   = (const float*)d_in[1];
    const float* wk   = (const float*)d_in[2];
    const float* wv   = (const float*)d_in[3];
    const float* wo   = (const float*)d_in[4];
    const float* rope = (const float*)d_in[5];
    const int* anchors = (const int*)d_in[6];
    float* out = (float*)d_out;

    const int kanch = in_sizes[6] / (H_NUM * T_NUM);  // 8

    float *qp, *kp, *vp, *ap;
    cudaGetSymbolAddress((void**)&qp, g_q);
    cudaGetSymbolAddress((void**)&kp, g_k);
    cudaGetSymbolAddress((void**)&vp, g_v);
    cudaGetSymbolAddress((void**)&ap, g_att);

    const size_t attn_smem = (2 * 128 * 129 + 128 * 128) * sizeof(float);
    cudaFuncSetAttribute(attn_kernel,
                         cudaFuncAttributeMaxDynamicSharedMemorySize,
                         (int)attn_smem);

    dim3 gblock(256);
    dim3 ggrid(E_DIM / 128, S_DIM / 128);  // (16, 32)

    // QKV projections (+RoPE for Q,K), head-major scratch
    gemm128_kernel<<<ggrid, gblock>>>(x, wq, qp, rope, 2);
    gemm128_kernel<<<ggrid, gblock>>>(x, wk, kp, rope, 2);
    gemm128_kernel<<<ggrid, gblock>>>(x, wv, vp, rope, 1);

    // Block-sparse attention
    dim3 agrid(T_NUM, H_NUM);  // (32, 16)
    attn_kernel<<<agrid, 256, attn_smem>>>(anchors, kanch);

    // Output projection -> d_out
    gemm128_kernel<<<ggrid, gblock>>>(ap, wo, out, nullptr, 0);
}

// round 3
// speedup vs baseline: 1.7923x; 1.7923x over previous
#include <cuda_runtime.h>
#include <cuda_bf16.h>
#include <math.h>
#include <stdint.h>

#define S_DIM 4096
#define E_DIM 2048
#define H_NUM 16
#define D_HEAD 128
#define T_NUM 32

// ---------------------------------------------------------------------------
// Scratch (__device__ globals; allocation-free rule)
// ---------------------------------------------------------------------------
__device__ float g_q[H_NUM * S_DIM * D_HEAD];
__device__ float g_k[H_NUM * S_DIM * D_HEAD];
__device__ float g_v[H_NUM * S_DIM * D_HEAD];

__device__ __nv_bfloat16 g_x_hi[S_DIM * E_DIM];
__device__ __nv_bfloat16 g_x_lo[S_DIM * E_DIM];
__device__ __nv_bfloat16 g_wqT_hi[E_DIM * E_DIM];
__device__ __nv_bfloat16 g_wqT_lo[E_DIM * E_DIM];
__device__ __nv_bfloat16 g_wkT_hi[E_DIM * E_DIM];
__device__ __nv_bfloat16 g_wkT_lo[E_DIM * E_DIM];
__device__ __nv_bfloat16 g_wvT_hi[E_DIM * E_DIM];
__device__ __nv_bfloat16 g_wvT_lo[E_DIM * E_DIM];
__device__ __nv_bfloat16 g_woT_hi[E_DIM * E_DIM];
__device__ __nv_bfloat16 g_woT_lo[E_DIM * E_DIM];
__device__ __nv_bfloat16 g_att_hi[S_DIM * E_DIM];
__device__ __nv_bfloat16 g_att_lo[S_DIM * E_DIM];

// ---------------------------------------------------------------------------
// base-ISA PTX helpers (NO tcgen05/TMA: harness compiles for compute_103)
// ---------------------------------------------------------------------------
__device__ __forceinline__ uint32_t smem_u32(const void* p) {
    uint32_t a;
    asm("{ .reg .u64 t; cvta.to.shared.u64 t, %1; cvt.u32.u64 %0, t; }" : "=r"(a) : "l"(p));
    return a;
}

#define CP_ASYNC16(dst, src) \
    asm volatile("cp.async.cg.shared.global [%0], [%1], 16;" :: "r"(dst), "l"(src))
#define CP_COMMIT() asm volatile("cp.async.commit_group;" ::: "memory")
#define CP_WAIT1() asm volatile("cp.async.wait_group 1;" ::: "memory")
#define CP_WAIT0() asm volatile("cp.async.wait_group 0;" ::: "memory")

#define LDSM4(r0, r1, r2, r3, addr) \
    asm volatile("ldmatrix.sync.aligned.m8n8.x4.shared.b16 {%0,%1,%2,%3}, [%4];" \
        : "=r"(r0), "=r"(r1), "=r"(r2), "=r"(r3) : "r"(addr))

#define MMA16816(d, a, b) \
    asm volatile("mma.sync.aligned.m16n8k16.row.col.f32.bf16.bf16.f32 " \
        "{%0,%1,%2,%3}, {%4,%5,%6,%7}, {%8,%9}, {%0,%1,%2,%3};" \
        : "+f"((d)[0]), "+f"((d)[1]), "+f"((d)[2]), "+f"((d)[3]) \
        : "r"((a)[0]), "r"((a)[1]), "r"((a)[2]), "r"((a)[3]), \
          "r"((b)[0]), "r"((b)[1]))

// ---------------------------------------------------------------------------
// fp32 -> bf16 hi/lo split (element-wise)
// ---------------------------------------------------------------------------
__global__ void split_kernel(const float* __restrict__ in,
                             __nv_bfloat16* __restrict__ hi,
                             __nv_bfloat16* __restrict__ lo, int n)
{
    int i = (blockIdx.x * blockDim.x + threadIdx.x) * 4;
    if (i >= n) return;
    float4 v = *(const float4*)(in + i);
    __nv_bfloat16 h0 = __float2bfloat16(v.x), h1 = __float2bfloat16(v.y);
    __nv_bfloat16 h2 = __float2bfloat16(v.z), h3 = __float2bfloat16(v.w);
    __nv_bfloat162 hA, hB, lA, lB;
    hA.x = h0; hA.y = h1; hB.x = h2; hB.y = h3;
    lA.x = __float2bfloat16(v.x - __bfloat162float(h0));
    lA.y = __float2bfloat16(v.y - __bfloat162float(h1));
    lB.x = __float2bfloat16(v.z - __bfloat162float(h2));
    lB.y = __float2bfloat16(v.w - __bfloat162float(h3));
    *(__nv_bfloat162*)(hi + i) = hA;
    *(__nv_bfloat162*)(hi + i + 2) = hB;
    *(__nv_bfloat162*)(lo + i) = lA;
    *(__nv_bfloat162*)(lo + i + 2) = lB;
}

// ---------------------------------------------------------------------------
// transpose w[K=2048, N=2048] -> wT[N, K] with bf16 hi/lo split
// ---------------------------------------------------------------------------
__global__ void transpose_split_kernel(const float* __restrict__ w,
                                       __nv_bfloat16* __restrict__ hiT,
                                       __nv_bfloat16* __restrict__ loT)
{
    __shared__ float tile[32][33];
    int n = blockIdx.x * 32 + threadIdx.x;
    int k0 = blockIdx.y * 32;
#pragma unroll
    for (int j = 0; j < 32; j += 8)
        tile[threadIdx.y + j][threadIdx.x] = w[(k0 + threadIdx.y + j) * E_DIM + n];
    __syncthreads();
#pragma unroll
    for (int j = 0; j < 32; j += 8) {
        int orow = blockIdx.x * 32 + threadIdx.y + j;
        int ocol = k0 + threadIdx.x;
        float v = tile[threadIdx.x][threadIdx.y + j];
        __nv_bfloat16 h = __float2bfloat16(v);
        hiT[orow * E_DIM + ocol] = h;
        loT[orow * E_DIM + ocol] = __float2bfloat16(v - __bfloat162float(h));
    }
}

// ---------------------------------------------------------------------------
// HMMA split-bf16 GEMM: C[4096,2048] = A[4096,2048] @ B, B given as BT[N,K].
// CTA 128x128, K-chunk 64, cp.async double buffer, mma.sync m16n8k16.
// mode 0: row-major fp32 out[M,2048]; mode 1: head-major; mode 2: +RoPE
// ---------------------------------------------------------------------------
#define ROW_B 144                    // padded smem row bytes (64 bf16 + 8 pad)
#define TILE_B (128 * ROW_B)         // 18432
#define STAGE_B (4 * TILE_B)         // 73728: Ah, Al, Bh, Bl
#define GEMM_SMEM (2 * STAGE_B)      // 147456

__global__ __launch_bounds__(256, 1)
void gemm_mma(const __nv_bfloat16* __restrict__ Ahi, const __nv_bfloat16* __restrict__ Alo,
              const __nv_bfloat16* __restrict__ Bhi, const __nv_bfloat16* __restrict__ Blo,
              float* __restrict__ out, const float* __restrict__ rope, int mode)
{
    extern __shared__ char smem[];
    const uint32_t smem_base = smem_u32(smem);
    const int tid = threadIdx.x;
    const int wid = tid >> 5;
    const int lane = tid & 31;
    const int m0 = blockIdx.y * 128;
    const int n0 = blockIdx.x * 128;
    const int wM = wid >> 2;         // 0..1
    const int wN = wid & 3;          // 0..3

    const char* srcs[4] = {
        (const char*)(Ahi + (size_t)m0 * E_DIM),
        (const char*)(Alo + (size_t)m0 * E_DIM),
        (const char*)(Bhi + (size_t)n0 * E_DIM),
        (const char*)(Blo + (size_t)n0 * E_DIM)
    };

    // --- loader: one 64-wide k-chunk (4 tiles of 128 rows x 128B) ---
    auto issue_chunk = [&](int c, int p) {
        uint32_t sb = smem_base + p * STAGE_B;
#pragma unroll
        for (int t = 0; t < 4; t++) {
#pragma unroll
            for (int i = 0; i < 4; i++) {
                int idx = tid + i * 256;          // 0..1023
                int row = idx >> 3;
                int c16 = idx & 7;
                uint32_t dst = sb + t * TILE_B + row * ROW_B + c16 * 16;
                const char* src = srcs[t] + (size_t)row * 4096 + c * 128 + c16 * 16;
                CP_ASYNC16(dst, src);
            }
        }
    };

    float acc[4][4][4];
#pragma unroll
    for (int mt = 0; mt < 4; mt++)
#pragma unroll
        for (int nt = 0; nt < 4; nt++)
#pragma unroll
            for (int e = 0; e < 4; e++) acc[mt][nt][e] = 0.0f;

    // ldmatrix lane addressing
    const int a_row = (lane & 15);
    const int a_kb = (lane >> 4) * 16;
    const int b_nrow = (lane & 7) | ((lane & 16) >> 1);
    const int b_kb = (lane & 8) ? 16 : 0;

    issue_chunk(0, 0);
    CP_COMMIT();

    for (int c = 0; c < 32; c++) {
        if (c + 1 < 32) {
            issue_chunk(c + 1, (c + 1) & 1);
            CP_COMMIT();
            CP_WAIT1();
        } else {
            CP_WAIT0();
        }
        __syncthreads();

        uint32_t sb = smem_base + (c & 1) * STAGE_B;
        uint32_t aH = sb + (wM * 64 + a_row) * ROW_B + a_kb;
        uint32_t aL = aH + TILE_B;
        uint32_t bH = sb + 2 * TILE_B + (wN * 32 + b_nrow) * ROW_B + b_kb;
        uint32_t bL = bH + TILE_B;

#pragma unroll
        for (int ks = 0; ks < 4; ks++) {
            uint32_t ah[4][4], al[4][4], bh[4][2], bl[4][2];
#pragma unroll
            for (int mt = 0; mt < 4; mt++) {
                LDSM4(ah[mt][0], ah[mt][1], ah[mt][2], ah[mt][3],
                      aH + mt * (16 * ROW_B) + ks * 32);
                LDSM4(al[mt][0], al[mt][1], al[mt][2], al[mt][3],
                      aL + mt * (16 * ROW_B) + ks * 32);
            }
#pragma unroll
            for (int bt = 0; bt < 2; bt++) {
                LDSM4(bh[bt * 2][0], bh[bt * 2][1], bh[bt * 2 + 1][0], bh[bt * 2 + 1][1],
                      bH + bt * (16 * ROW_B) + ks * 32);
                LDSM4(bl[bt * 2][0], bl[bt * 2][1], bl[bt * 2 + 1][0], bl[bt * 2 + 1][1],
                      bL + bt * (16 * ROW_B) + ks * 32);
            }
#pragma unroll
            for (int mt = 0; mt < 4; mt++)
#pragma unroll
                for (int nt = 0; nt < 4; nt++) {
                    MMA16816(acc[mt][nt], ah[mt], bh[nt]);
                    MMA16816(acc[mt][nt], ah[mt], bl[nt]);
                    MMA16816(acc[mt][nt], al[mt], bh[nt]);
                }
        }
        __syncthreads();
    }

    // --- epilogue through smem (RoPE pairs d/d+64 cross N-warps otherwise) ---
    float* csm = (float*)smem;     // [128][132]
    const int g = lane >> 2;
    const int tg = lane & 3;
#pragma unroll
    for (int mt = 0; mt < 4; mt++)
#pragma unroll
        for (int nt = 0; nt < 4; nt++) {
            int r = wM * 64 + mt * 16 + g;
            int col = wN * 32 + nt * 8 + tg * 2;
            csm[r * 132 + col]           = acc[mt][nt][0];
            csm[r * 132 + col + 1]       = acc[mt][nt][1];
            csm[(r + 8) * 132 + col]     = acc[mt][nt][2];
            csm[(r + 8) * 132 + col + 1] = acc[mt][nt][3];
        }
    __syncthreads();

#pragma unroll 4
    for (int it = 0; it < 32; it++) {
        int idx = tid + it * 256;          // 0..8191
        int row = idx >> 6;
        int d = idx & 63;
        float lo = csm[row * 132 + d];
        float hi = csm[row * 132 + d + 64];
        int s = m0 + row;
        if (mode == 0) {
            float* orow = out + (size_t)s * E_DIM + n0;
            orow[d] = lo;
            orow[d + 64] = hi;
        } else {
            if (mode == 2) {
                float ang = rope[s * (D_HEAD / 2) + d];
                float sn, cs;
                __sincosf(ang, &sn, &cs);
                float nlo = lo * cs - hi * sn;
                float nhi = hi * cs + lo * sn;
                lo = nlo; hi = nhi;
            }
            const int h = n0 >> 7;
            float* orow = out + ((size_t)h * S_DIM + s) * D_HEAD;
            orow[d] = lo;
            orow[d + 64] = hi;
        }
    }
}

// ---------------------------------------------------------------------------
// Block-sparse attention (fp32, register-blocked), one CTA per (q-tile, head).
// Epilogue writes bf16 hi/lo split directly for the out-projection GEMM.
// ---------------------------------------------------------------------------
#define NEG_BIG (-1e10f)

__global__ __launch_bounds__(256, 1)
void attn_kernel(const int* __restrict__ anchors, int kanch)
{
    extern __shared__ float sm[];
    float (*Qs)[129] = (float(*)[129])sm;
    float (*KP)[129] = (float(*)[129])(sm + 128 * 129);
    float (*Vs)[128] = (float(*)[128])(sm + 2 * 128 * 129);

    const int t = blockIdx.x;
    const int h = blockIdx.y;
    const int tid = threadIdx.x;
    const int tx = tid & 15;
    const int ty = tid >> 4;
    const float sm_scale = 0.088388347648318447f;  // 1/sqrt(128)

    const float* qg = g_q + (h * S_DIM + t * 128) * D_HEAD;
    for (int i = tid; i < 128 * 32; i += 256) {
        int q = i >> 5;
        int dg = (i & 31) * 4;
        float4 v = *(const float4*)(qg + q * 128 + dg);
        Qs[dg + 0][q] = v.x;
        Qs[dg + 1][q] = v.y;
        Qs[dg + 2][q] = v.z;
        Qs[dg + 3][q] = v.w;
    }

    int r[8], cc[8];
#pragma unroll
    for (int i = 0; i < 4; i++) {
        r[i] = ty * 4 + i;
        r[4 + i] = 64 + ty * 4 + i;
        cc[i] = tx * 4 + i;
        cc[4 + i] = 64 + tx * 4 + i;
    }

    float O[8][8];
    float mrow[8], lrow[8];
#pragma unroll
    for (int i = 0; i < 8; i++) {
        mrow[i] = -1e30f;
        lrow[i] = 0.0f;
#pragma unroll
        for (int j = 0; j < 8; j++) O[i][j] = 0.0f;
    }

    for (int it = 0; it <= kanch; it++) {
        int tile = (it < kanch) ? anchors[(h * T_NUM + t) * kanch + it] : t;

        __syncthreads();
        const float* kg = g_k + (h * S_DIM + tile * 128) * D_HEAD;
        const float* vg = g_v + (h * S_DIM + tile * 128) * D_HEAD;
        for (int i = tid; i < 128 * 32; i += 256) {
            int kq = i >> 5;
            int dg = (i & 31) * 4;
            float4 kv = *(const float4*)(kg + kq * 128 + dg);
            KP[dg + 0][kq] = kv.x;
            KP[dg + 1][kq] = kv.y;
            KP[dg + 2][kq] = kv.z;
            KP[dg + 3][kq] = kv.w;
            *(float4*)&Vs[kq][dg] = *(const float4*)(vg + kq * 128 + dg);
        }
        __syncthreads();

        float sreg[8][8];
#pragma unroll
        for (int i = 0; i < 8; i++)
#pragma unroll
            for (int j = 0; j < 8; j++) sreg[i][j] = 0.0f;

        for (int d = 0; d < 128; d++) {
            float a[8], b[8];
#pragma unroll
            for (int i = 0; i < 8; i++) a[i] = Qs[d][r[i]];
#pragma unroll
            for (int j = 0; j < 8; j++) b[j] = KP[d][cc[j]];
#pragma unroll
            for (int i = 0; i < 8; i++)
#pragma unroll
                for (int j = 0; j < 8; j++)
                    sreg[i][j] = fmaf(a[i], b[j], sreg[i][j]);
        }

        const int kbase = tile * 128;
        const int qbase = t * 128;
#pragma unroll
        for (int i = 0; i < 8; i++) {
            int qpos = qbase + r[i];
#pragma unroll
            for (int j = 0; j < 8; j++) {
                float v = sreg[i][j] * sm_scale;
                if (kbase + cc[j] > qpos) v = NEG_BIG;
                sreg[i][j] = v;
            }
        }

#pragma unroll
        for (int i = 0; i < 8; i++) {
            float mx = sreg[i][0];
#pragma unroll
            for (int j = 1; j < 8; j++) mx = fmaxf(mx, sreg[i][j]);
#pragma unroll
            for (int off = 1; off < 16; off <<= 1)
                mx = fmaxf(mx, __shfl_xor_sync(0xffffffffu, mx, off));
            float mnew = fmaxf(mrow[i], mx);
            float fac = __expf(mrow[i] - mnew);
            float ls = 0.0f;
#pragma unroll
            for (int j = 0; j < 8; j++) {
                sreg[i][j] = __expf(sreg[i][j] - mnew);
                ls += sreg[i][j];
            }
#pragma unroll
            for (int off = 1; off < 16; off <<= 1)
                ls += __shfl_xor_sync(0xffffffffu, ls, off);
            lrow[i] = lrow[i] * fac + ls;
            mrow[i] = mnew;
#pragma unroll
            for (int j = 0; j < 8; j++) O[i][j] *= fac;
        }

        __syncthreads();
#pragma unroll
        for (int i = 0; i < 8; i++)
#pragma unroll
            for (int j = 0; j < 8; j++) KP[cc[j]][r[i]] = sreg[i][j];
        __syncthreads();

        for (int kk = 0; kk < 128; kk++) {
            float a[8], b[8];
#pragma unroll
            for (int i = 0; i < 8; i++) a[i] = KP[kk][r[i]];
#pragma unroll
            for (int j = 0; j < 8; j++) b[j] = Vs[kk][cc[j]];
#pragma unroll
            for (int i = 0; i < 8; i++)
#pragma unroll
                for (int j = 0; j < 8; j++)
                    O[i][j] = fmaf(a[i], b[j], O[i][j]);
        }
    }

    // normalize + bf16 hi/lo split store to [S, H*D] for the out-projection
    __nv_bfloat16* oh = g_att_hi + (size_t)(t * 128) * E_DIM + h * D_HEAD;
    __nv_bfloat16* ol = g_att_lo + (size_t)(t * 128) * E_DIM + h * D_HEAD;
#pragma unroll
    for (int i = 0; i < 8; i++) {
        float inv = 1.0f / lrow[i];
        __nv_bfloat16* hrow = oh + (size_t)r[i] * E_DIM;
        __nv_bfloat16* lrow2 = ol + (size_t)r[i] * E_DIM;
#pragma unroll
        for (int j = 0; j < 8; j++) {
            float o = O[i][j] * inv;
            __nv_bfloat16 hv = __float2bfloat16(o);
            hrow[cc[j]] = hv;
            lrow2[cc[j]] = __float2bfloat16(o - __bfloat162float(hv));
        }
    }
}

// ---------------------------------------------------------------------------
extern "C" void kernel_launch(void* const* d_in, const int* in_sizes, int n_in,
                              void* d_out, int out_size)
{
    const float* x    = (const float*)d_in[0];
    const float* wq   = (const float*)d_in[1];
    const float* wk   = (const float*)d_in[2];
    const float* wv   = (const float*)d_in[3];
    const float* wo   = (const float*)d_in[4];
    const float* rope = (const float*)d_in[5];
    const int* anchors = (const int*)d_in[6];
    float* out = (float*)d_out;

    const int kanch = in_sizes[6] / (H_NUM * T_NUM);  // 8

    float *qp, *kp, *vp;
    cudaGetSymbolAddress((void**)&qp, g_q);
    cudaGetSymbolAddress((void**)&kp, g_k);
    cudaGetSymbolAddress((void**)&vp, g_v);
    __nv_bfloat16 *xh, *xl, *qTh, *qTl, *kTh, *kTl, *vTh, *vTl, *oTh, *oTl, *ah, *al;
    cudaGetSymbolAddress((void**)&xh, g_x_hi);
    cudaGetSymbolAddress((void**)&xl, g_x_lo);
    cudaGetSymbolAddress((void**)&qTh, g_wqT_hi);
    cudaGetSymbolAddress((void**)&qTl, g_wqT_lo);
    cudaGetSymbolAddress((void**)&kTh, g_wkT_hi);
    cudaGetSymbolAddress((void**)&kTl, g_wkT_lo);
    cudaGetSymbolAddress((void**)&vTh, g_wvT_hi);
    cudaGetSymbolAddress((void**)&vTl, g_wvT_lo);
    cudaGetSymbolAddress((void**)&oTh, g_woT_hi);
    cudaGetSymbolAddress((void**)&oTl, g_woT_lo);
    cudaGetSymbolAddress((void**)&ah, g_att_hi);
    cudaGetSymbolAddress((void**)&al, g_att_lo);

    cudaFuncSetAttribute(gemm_mma, cudaFuncAttributeMaxDynamicSharedMemorySize, GEMM_SMEM);
    const size_t attn_smem = (2 * 128 * 129 + 128 * 128) * sizeof(float);
    cudaFuncSetAttribute(attn_kernel, cudaFuncAttributeMaxDynamicSharedMemorySize, (int)attn_smem);

    // 1. split x -> bf16 hi/lo
    split_kernel<<<(S_DIM * E_DIM / 4 + 255) / 256, 256>>>(x, xh, xl, S_DIM * E_DIM);

    // 2. transpose + split weights -> [N, K] bf16 hi/lo
    dim3 tgrid(E_DIM / 32, E_DIM / 32), tblk(32, 8);
    transpose_split_kernel<<<tgrid, tblk>>>(wq, qTh, qTl);
    transpose_split_kernel<<<tgrid, tblk>>>(wk, kTh, kTl);
    transpose_split_kernel<<<tgrid, tblk>>>(wv, vTh, vTl);
    transpose_split_kernel<<<tgrid, tblk>>>(wo, oTh, oTl);

    // 3. HMMA QKV projections (RoPE fused for Q,K), head-major fp32 scratch
    dim3 ggrid(E_DIM / 128, S_DIM / 128);  // (16, 32)
    gemm_mma<<<ggrid, 256, GEMM_SMEM>>>(xh, xl, qTh, qTl, qp, rope, 2);
    gemm_mma<<<ggrid, 256, GEMM_SMEM>>>(xh, xl, kTh, kTl, kp, rope, 2);
    gemm_mma<<<ggrid, 256, GEMM_SMEM>>>(xh, xl, vTh, vTl, vp, nullptr, 1);

    // 4. block-sparse attention (fp32) -> bf16 hi/lo att
    dim3 agrid(T_NUM, H_NUM);
    attn_kernel<<<agrid, 256, attn_smem>>>(anchors, kanch);

    // 5. out projection -> d_out
    gemm_mma<<<ggrid, 256, GEMM_SMEM>>>(ah, al, oTh, oTl, out, nullptr, 0);
}

// round 4
// speedup vs baseline: 2.7823x; 1.5524x over previous
#include <cuda_runtime.h>
#include <cuda_bf16.h>
#include <math.h>
#include <stdint.h>

#define S_DIM 4096
#define E_DIM 2048
#define H_NUM 16
#define D_HEAD 128
#define T_NUM 32

// ---------------------------------------------------------------------------
// Scratch (__device__ globals; allocation-free rule)
// ---------------------------------------------------------------------------
__device__ __nv_bfloat16 g_x_hi[S_DIM * E_DIM];
__device__ __nv_bfloat16 g_x_lo[S_DIM * E_DIM];
__device__ __nv_bfloat16 g_wqT_hi[E_DIM * E_DIM];
__device__ __nv_bfloat16 g_wqT_lo[E_DIM * E_DIM];
__device__ __nv_bfloat16 g_wkT_hi[E_DIM * E_DIM];
__device__ __nv_bfloat16 g_wkT_lo[E_DIM * E_DIM];
__device__ __nv_bfloat16 g_wvT_hi[E_DIM * E_DIM];
__device__ __nv_bfloat16 g_wvT_lo[E_DIM * E_DIM];
__device__ __nv_bfloat16 g_woT_hi[E_DIM * E_DIM];
__device__ __nv_bfloat16 g_woT_lo[E_DIM * E_DIM];
// head-major bf16 hi/lo QKV (RoPE already applied to Q,K)
__device__ __nv_bfloat16 g_qh[H_NUM * S_DIM * D_HEAD];
__device__ __nv_bfloat16 g_ql[H_NUM * S_DIM * D_HEAD];
__device__ __nv_bfloat16 g_kh[H_NUM * S_DIM * D_HEAD];
__device__ __nv_bfloat16 g_kl[H_NUM * S_DIM * D_HEAD];
__device__ __nv_bfloat16 g_vh[H_NUM * S_DIM * D_HEAD];
__device__ __nv_bfloat16 g_vl[H_NUM * S_DIM * D_HEAD];
__device__ __nv_bfloat16 g_att_hi[S_DIM * E_DIM];
__device__ __nv_bfloat16 g_att_lo[S_DIM * E_DIM];

// ---------------------------------------------------------------------------
// base-ISA PTX helpers (compute_103 virtual arch: no tcgen05/TMA)
// ---------------------------------------------------------------------------
__device__ __forceinline__ uint32_t smem_u32(const void* p) {
    uint32_t a;
    asm("{ .reg .u64 t; cvta.to.shared.u64 t, %1; cvt.u32.u64 %0, t; }" : "=r"(a) : "l"(p));
    return a;
}

#define CP_ASYNC16(dst, src) \
    asm volatile("cp.async.cg.shared.global [%0], [%1], 16;" :: "r"(dst), "l"(src))
#define CP_COMMIT() asm volatile("cp.async.commit_group;" ::: "memory")
#define CP_WAIT1() asm volatile("cp.async.wait_group 1;" ::: "memory")
#define CP_WAIT0() asm volatile("cp.async.wait_group 0;" ::: "memory")

#define LDSM4(r0, r1, r2, r3, addr) \
    asm volatile("ldmatrix.sync.aligned.m8n8.x4.shared.b16 {%0,%1,%2,%3}, [%4];" \
        : "=r"(r0), "=r"(r1), "=r"(r2), "=r"(r3) : "r"(addr))
#define LDSM4T(r0, r1, r2, r3, addr) \
    asm volatile("ldmatrix.sync.aligned.m8n8.x4.trans.shared.b16 {%0,%1,%2,%3}, [%4];" \
        : "=r"(r0), "=r"(r1), "=r"(r2), "=r"(r3) : "r"(addr))

#define MMA16816(d, a, b) \
    asm volatile("mma.sync.aligned.m16n8k16.row.col.f32.bf16.bf16.f32 " \
        "{%0,%1,%2,%3}, {%4,%5,%6,%7}, {%8,%9}, {%0,%1,%2,%3};" \
        : "+f"((d)[0]), "+f"((d)[1]), "+f"((d)[2]), "+f"((d)[3]) \
        : "r"((a)[0]), "r"((a)[1]), "r"((a)[2]), "r"((a)[3]), \
          "r"((b)[0]), "r"((b)[1]))

__device__ __forceinline__ uint32_t pack_bf16x2(float a, float b) {
    __nv_bfloat162 v = __float22bfloat162_rn(make_float2(a, b));
    return *(uint32_t*)&v;
}
__device__ __forceinline__ uint32_t pack_bf16x2_res(float a, float b, uint32_t hibits) {
    __nv_bfloat162 h = *(__nv_bfloat162*)&hibits;
    return pack_bf16x2(a - __bfloat162float(h.x), b - __bfloat162float(h.y));
}

// ---------------------------------------------------------------------------
// fp32 -> bf16 hi/lo split (element-wise)
// ---------------------------------------------------------------------------
__global__ void split_kernel(const float* __restrict__ in,
                             __nv_bfloat16* __restrict__ hi,
                             __nv_bfloat16* __restrict__ lo, int n)
{
    int i = (blockIdx.x * blockDim.x + threadIdx.x) * 4;
    if (i >= n) return;
    float4 v = *(const float4*)(in + i);
    __nv_bfloat16 h0 = __float2bfloat16(v.x), h1 = __float2bfloat16(v.y);
    __nv_bfloat16 h2 = __float2bfloat16(v.z), h3 = __float2bfloat16(v.w);
    __nv_bfloat162 hA, hB, lA, lB;
    hA.x = h0; hA.y = h1; hB.x = h2; hB.y = h3;
    lA.x = __float2bfloat16(v.x - __bfloat162float(h0));
    lA.y = __float2bfloat16(v.y - __bfloat162float(h1));
    lB.x = __float2bfloat16(v.z - __bfloat162float(h2));
    lB.y = __float2bfloat16(v.w - __bfloat162float(h3));
    *(__nv_bfloat162*)(hi + i) = hA;
    *(__nv_bfloat162*)(hi + i + 2) = hB;
    *(__nv_bfloat162*)(lo + i) = lA;
    *(__nv_bfloat162*)(lo + i + 2) = lB;
}

// ---------------------------------------------------------------------------
// transpose w[K=2048, N=2048] -> wT[N, K] with bf16 hi/lo split
// ---------------------------------------------------------------------------
__global__ void transpose_split_kernel(const float* __restrict__ w,
                                       __nv_bfloat16* __restrict__ hiT,
                                       __nv_bfloat16* __restrict__ loT)
{
    __shared__ float tile[32][33];
    int n = blockIdx.x * 32 + threadIdx.x;
    int k0 = blockIdx.y * 32;
#pragma unroll
    for (int j = 0; j < 32; j += 8)
        tile[threadIdx.y + j][threadIdx.x] = w[(k0 + threadIdx.y + j) * E_DIM + n];
    __syncthreads();
#pragma unroll
    for (int j = 0; j < 32; j += 8) {
        int orow = blockIdx.x * 32 + threadIdx.y + j;
        int ocol = k0 + threadIdx.x;
        float v = tile[threadIdx.x][threadIdx.y + j];
        __nv_bfloat16 h = __float2bfloat16(v);
        hiT[orow * E_DIM + ocol] = h;
        loT[orow * E_DIM + ocol] = __float2bfloat16(v - __bfloat162float(h));
    }
}

// ---------------------------------------------------------------------------
// HMMA split-bf16 GEMM (CTA 128x128, K-chunk 64, cp.async double buffer)
// mode 0: fp32 row-major out[M,2048]
// mode 1: bf16 hi/lo head-major out[h][s][d]
// mode 2: bf16 hi/lo head-major + RoPE
// ---------------------------------------------------------------------------
#define ROW_B 144
#define TILE_B (128 * ROW_B)
#define STAGE_B (4 * TILE_B)
#define GEMM_SMEM (2 * STAGE_B)

__global__ __launch_bounds__(256, 1)
void gemm_mma(const __nv_bfloat16* __restrict__ Ahi, const __nv_bfloat16* __restrict__ Alo,
              const __nv_bfloat16* __restrict__ Bhi, const __nv_bfloat16* __restrict__ Blo,
              float* __restrict__ outf,
              __nv_bfloat16* __restrict__ outh, __nv_bfloat16* __restrict__ outl,
              const float* __restrict__ rope, int mode)
{
    extern __shared__ char smem[];
    const uint32_t smem_base = smem_u32(smem);
    const int tid = threadIdx.x;
    const int wid = tid >> 5;
    const int lane = tid & 31;
    const int m0 = blockIdx.y * 128;
    const int n0 = blockIdx.x * 128;
    const int wM = wid >> 2;
    const int wN = wid & 3;

    const char* srcs[4] = {
        (const char*)(Ahi + (size_t)m0 * E_DIM),
        (const char*)(Alo + (size_t)m0 * E_DIM),
        (const char*)(Bhi + (size_t)n0 * E_DIM),
        (const char*)(Blo + (size_t)n0 * E_DIM)
    };

    auto issue_chunk = [&](int c, int p) {
        uint32_t sb = smem_base + p * STAGE_B;
#pragma unroll
        for (int t = 0; t < 4; t++) {
#pragma unroll
            for (int i = 0; i < 4; i++) {
                int idx = tid + i * 256;
                int row = idx >> 3;
                int c16 = idx & 7;
                uint32_t dst = sb + t * TILE_B + row * ROW_B + c16 * 16;
                const char* src = srcs[t] + (size_t)row * 4096 + c * 128 + c16 * 16;
                CP_ASYNC16(dst, src);
            }
        }
    };

    float acc[4][4][4];
#pragma unroll
    for (int mt = 0; mt < 4; mt++)
#pragma unroll
        for (int nt = 0; nt < 4; nt++)
#pragma unroll
            for (int e = 0; e < 4; e++) acc[mt][nt][e] = 0.0f;

    const int a_row = (lane & 15);
    const int a_kb = (lane >> 4) * 16;
    const int b_nrow = (lane & 7) | ((lane & 16) >> 1);
    const int b_kb = (lane & 8) ? 16 : 0;

    issue_chunk(0, 0);
    CP_COMMIT();

    for (int c = 0; c < 32; c++) {
        if (c + 1 < 32) {
            issue_chunk(c + 1, (c + 1) & 1);
            CP_COMMIT();
            CP_WAIT1();
        } else {
            CP_WAIT0();
        }
        __syncthreads();

        uint32_t sb = smem_base + (c & 1) * STAGE_B;
        uint32_t aH = sb + (wM * 64 + a_row) * ROW_B + a_kb;
        uint32_t aL = aH + TILE_B;
        uint32_t bH = sb + 2 * TILE_B + (wN * 32 + b_nrow) * ROW_B + b_kb;
        uint32_t bL = bH + TILE_B;

#pragma unroll
        for (int ks = 0; ks < 4; ks++) {
            uint32_t ah[4][4], al[4][4], bh[4][2], bl[4][2];
#pragma unroll
            for (int mt = 0; mt < 4; mt++) {
                LDSM4(ah[mt][0], ah[mt][1], ah[mt][2], ah[mt][3],
                      aH + mt * (16 * ROW_B) + ks * 32);
                LDSM4(al[mt][0], al[mt][1], al[mt][2], al[mt][3],
                      aL + mt * (16 * ROW_B) + ks * 32);
            }
#pragma unroll
            for (int bt = 0; bt < 2; bt++) {
                LDSM4(bh[bt * 2][0], bh[bt * 2][1], bh[bt * 2 + 1][0], bh[bt * 2 + 1][1],
                      bH + bt * (16 * ROW_B) + ks * 32);
                LDSM4(bl[bt * 2][0], bl[bt * 2][1], bl[bt * 2 + 1][0], bl[bt * 2 + 1][1],
                      bL + bt * (16 * ROW_B) + ks * 32);
            }
#pragma unroll
            for (int mt = 0; mt < 4; mt++)
#pragma unroll
                for (int nt = 0; nt < 4; nt++) {
                    MMA16816(acc[mt][nt], ah[mt], bh[nt]);
                    MMA16816(acc[mt][nt], ah[mt], bl[nt]);
                    MMA16816(acc[mt][nt], al[mt], bh[nt]);
                }
        }
        __syncthreads();
    }

    // epilogue through smem so RoPE pairs d/d+64 are thread-local
    float* csm = (float*)smem;     // [128][132]
    const int g = lane >> 2;
    const int tg = lane & 3;
#pragma unroll
    for (int mt = 0; mt < 4; mt++)
#pragma unroll
        for (int nt = 0; nt < 4; nt++) {
            int r = wM * 64 + mt * 16 + g;
            int col = wN * 32 + nt * 8 + tg * 2;
            csm[r * 132 + col]           = acc[mt][nt][0];
            csm[r * 132 + col + 1]       = acc[mt][nt][1];
            csm[(r + 8) * 132 + col]     = acc[mt][nt][2];
            csm[(r + 8) * 132 + col + 1] = acc[mt][nt][3];
        }
    __syncthreads();

#pragma unroll 4
    for (int it = 0; it < 32; it++) {
        int idx = tid + it * 256;
        int row = idx >> 6;
        int d = idx & 63;
        float lo = csm[row * 132 + d];
        float hi = csm[row * 132 + d + 64];
        int s = m0 + row;
        if (mode == 0) {
            float* orow = outf + (size_t)s * E_DIM + n0;
            orow[d] = lo;
            orow[d + 64] = hi;
        } else {
            if (mode == 2) {
                float ang = rope[s * (D_HEAD / 2) + d];
                float sn, cs;
                __sincosf(ang, &sn, &cs);
                float nlo = lo * cs - hi * sn;
                float nhi = hi * cs + lo * sn;
                lo = nlo; hi = nhi;
            }
            const int h = n0 >> 7;
            size_t base = ((size_t)h * S_DIM + s) * D_HEAD;
            __nv_bfloat16 hl = __float2bfloat16(lo);
            __nv_bfloat16 hh = __float2bfloat16(hi);
            outh[base + d]      = hl;
            outh[base + d + 64] = hh;
            outl[base + d]      = __float2bfloat16(lo - __bfloat162float(hl));
            outl[base + d + 64] = __float2bfloat16(hi - __bfloat162float(hh));
        }
    }
}

// ---------------------------------------------------------------------------
// Block-sparse attention on mma.sync bf16 (FA2-style), CTA per (q-tile, head).
// Warp w owns query rows 16w..16w+15 across the full 128-key tile.
// Q,K,V in smem as hi/lo bf16, 256B XOR-swizzled rows. cp.async pipeline:
// prefetch next K during softmax/PV, next V during next tile's S.
// ---------------------------------------------------------------------------
#define NEG_BIG (-1e10f)
#define ATT_TILE 32768
#define ATT_SMEM (6 * ATT_TILE)   // 196608

__global__ __launch_bounds__(256, 1)
void attn_mma(const int* __restrict__ anchors, int kanch)
{
    extern __shared__ char smn[];
    const uint32_t base = smem_u32(smn);
    const uint32_t Qh = base,            Ql = base + ATT_TILE;
    const uint32_t Kh = base + 2*ATT_TILE, Kl = base + 3*ATT_TILE;
    const uint32_t Vh = base + 4*ATT_TILE, Vl = base + 5*ATT_TILE;

    const int t = blockIdx.x, h = blockIdx.y;
    const int tid = threadIdx.x;
    const int w = tid >> 5, lane = tid & 31;
    const int g = lane >> 2, tq = lane & 3;
    const float scale = 0.088388347648318447f;

    auto load_tile2 = [&](uint32_t dh, uint32_t dl,
                          const __nv_bfloat16* sh, const __nv_bfloat16* sl, int tile) {
        const char* ph = (const char*)(sh + ((size_t)h * S_DIM + (size_t)tile * 128) * D_HEAD);
        const char* pl = (const char*)(sl + ((size_t)h * S_DIM + (size_t)tile * 128) * D_HEAD);
        for (int i = tid; i < 2048; i += 256) {
            int row = i >> 4, c16 = i & 15;
            uint32_t off = row * 256 + ((c16 ^ (row & 7)) << 4);
            CP_ASYNC16(dh + off, ph + (size_t)row * 256 + c16 * 16);
            CP_ASYNC16(dl + off, pl + (size_t)row * 256 + c16 * 16);
        }
    };

    const int abase = (h * T_NUM + t) * kanch;
    int tile = (kanch > 0) ? anchors[abase] : t;

    // group0: Q + K0 ; group1: V0
    load_tile2(Qh, Ql, g_qh, g_ql, t);
    load_tile2(Kh, Kl, g_kh, g_kl, tile);
    CP_COMMIT();
    load_tile2(Vh, Vl, g_vh, g_vl, tile);
    CP_COMMIT();

    float o[16][4];
#pragma unroll
    for (int j = 0; j < 16; j++)
#pragma unroll
        for (int e = 0; e < 4; e++) o[j][e] = 0.0f;
    float m0 = -1e30f, m1 = -1e30f, l0 = 0.0f, l1 = 0.0f;

    const int wrow = w * 16;
    const int arow = wrow + (lane & 15);
    const int asw = arow & 7;
    const int ahc = lane >> 4;                       // 0/1: k half
    const int bnr = (lane & 7) | ((lane & 16) >> 1); // 0..15 n-row
    const int bhc = (lane & 8) >> 3;
    const int vrl = lane & 15;
    const int vhc = lane >> 4;

    for (int it = 0; it <= kanch; it++) {
        const int nx = (it + 1 < kanch) ? anchors[abase + it + 1] : t;
        const bool have_next = (it < kanch);

        CP_WAIT1();          // K_it (and Q on it==0) ready
        __syncthreads();

        // ---- S = Q K^T (3 split terms) ----
        float s[16][4];
#pragma unroll
        for (int j = 0; j < 16; j++)
#pragma unroll
            for (int e = 0; e < 4; e++) s[j][e] = 0.0f;

#pragma unroll
        for (int ks = 0; ks < 8; ks++) {
            uint32_t qh4[4], ql4[4];
            uint32_t aoff = arow * 256 + (((ks * 2 + ahc) ^ asw) << 4);
            LDSM4(qh4[0], qh4[1], qh4[2], qh4[3], Qh + aoff);
            LDSM4(ql4[0], ql4[1], ql4[2], ql4[3], Ql + aoff);
#pragma unroll
            for (int nb = 0; nb < 8; nb++) {
                int br = nb * 16 + bnr;
                uint32_t boff = br * 256 + (((ks * 2 + bhc) ^ (br & 7)) << 4);
                uint32_t kh4[4], kl4[4];
                LDSM4(kh4[0], kh4[1], kh4[2], kh4[3], Kh + boff);
                LDSM4(kl4[0], kl4[1], kl4[2], kl4[3], Kl + boff);
                uint32_t b0h[2] = {kh4[0], kh4[1]}, b1h[2] = {kh4[2], kh4[3]};
                uint32_t b0l[2] = {kl4[0], kl4[1]}, b1l[2] = {kl4[2], kl4[3]};
                MMA16816(s[2 * nb],     qh4, b0h);
                MMA16816(s[2 * nb],     qh4, b0l);
                MMA16816(s[2 * nb],     ql4, b0h);
                MMA16816(s[2 * nb + 1], qh4, b1h);
                MMA16816(s[2 * nb + 1], qh4, b1l);
                MMA16816(s[2 * nb + 1], ql4, b1h);
            }
        }
        __syncthreads();                 // all warps done reading K
        if (have_next) load_tile2(Kh, Kl, g_kh, g_kl, nx);   // prefetch K
        CP_COMMIT();

        // ---- mask + online softmax (quad shuffles only) ----
        const int qp0 = t * 128 + wrow + g;
        const int qp1 = qp0 + 8;
        const int kb = tile * 128 + 2 * tq;
        float mx0 = -1e30f, mx1 = -1e30f;
#pragma unroll
        for (int j = 0; j < 16; j++) {
            int kc = kb + 8 * j;
            s[j][0] = (kc     > qp0) ? NEG_BIG : s[j][0] * scale;
            s[j][1] = (kc + 1 > qp0) ? NEG_BIG : s[j][1] * scale;
            s[j][2] = (kc     > qp1) ? NEG_BIG : s[j][2] * scale;
            s[j][3] = (kc + 1 > qp1) ? NEG_BIG : s[j][3] * scale;
            mx0 = fmaxf(mx0, fmaxf(s[j][0], s[j][1]));
            mx1 = fmaxf(mx1, fmaxf(s[j][2], s[j][3]));
        }
        mx0 = fmaxf(mx0, __shfl_xor_sync(0xffffffffu, mx0, 1));
        mx0 = fmaxf(mx0, __shfl_xor_sync(0xffffffffu, mx0, 2));
        mx1 = fmaxf(mx1, __shfl_xor_sync(0xffffffffu, mx1, 1));
        mx1 = fmaxf(mx1, __shfl_xor_sync(0xffffffffu, mx1, 2));
        const float mn0 = fmaxf(m0, mx0), mn1 = fmaxf(m1, mx1);
        const float f0 = __expf(m0 - mn0), f1 = __expf(m1 - mn1);
        float ls0 = 0.0f, ls1 = 0.0f;
#pragma unroll
        for (int j = 0; j < 16; j++) {
            s[j][0] = __expf(s[j][0] - mn0);
            s[j][1] = __expf(s[j][1] - mn0);
            s[j][2] = __expf(s[j][2] - mn1);
            s[j][3] = __expf(s[j][3] - mn1);
            ls0 += s[j][0] + s[j][1];
            ls1 += s[j][2] + s[j][3];
        }
        ls0 += __shfl_xor_sync(0xffffffffu, ls0, 1);
        ls0 += __shfl_xor_sync(0xffffffffu, ls0, 2);
        ls1 += __shfl_xor_sync(0xffffffffu, ls1, 1);
        ls1 += __shfl_xor_sync(0xffffffffu, ls1, 2);
        l0 = l0 * f0 + ls0; l1 = l1 * f1 + ls1;
        m0 = mn0; m1 = mn1;
#pragma unroll
        for (int j = 0; j < 16; j++) {
            o[j][0] *= f0; o[j][1] *= f0;
            o[j][2] *= f1; o[j][3] *= f1;
        }

        CP_WAIT1();          // V_it ready (next-K group may still pend)
        __syncthreads();

        // ---- O += P V (3 split terms), P packed from S fragments ----
#pragma unroll
        for (int ks = 0; ks < 8; ks++) {
            uint32_t ph[4], pl[4];
            ph[0] = pack_bf16x2(s[2 * ks][0], s[2 * ks][1]);
            ph[1] = pack_bf16x2(s[2 * ks][2], s[2 * ks][3]);
            ph[2] = pack_bf16x2(s[2 * ks + 1][0], s[2 * ks + 1][1]);
            ph[3] = pack_bf16x2(s[2 * ks + 1][2], s[2 * ks + 1][3]);
            pl[0] = pack_bf16x2_res(s[2 * ks][0], s[2 * ks][1], ph[0]);
            pl[1] = pack_bf16x2_res(s[2 * ks][2], s[2 * ks][3], ph[1]);
            pl[2] = pack_bf16x2_res(s[2 * ks + 1][0], s[2 * ks + 1][1], ph[2]);
            pl[3] = pack_bf16x2_res(s[2 * ks + 1][2], s[2 * ks + 1][3], ph[3]);
            int vr = ks * 16 + vrl;
#pragma unroll
            for (int dd = 0; dd < 8; dd++) {
                uint32_t voff = vr * 256 + (((dd * 2 + vhc) ^ (vr & 7)) << 4);
                uint32_t vh4[4], vl4[4];
                LDSM4T(vh4[0], vh4[1], vh4[2], vh4[3], Vh + voff);
                LDSM4T(vl4[0], vl4[1], vl4[2], vl4[3], Vl + voff);
                uint32_t b0h[2] = {vh4[0], vh4[1]}, b1h[2] = {vh4[2], vh4[3]};
                uint32_t b0l[2] = {vl4[0], vl4[1]}, b1l[2] = {vl4[2], vl4[3]};
                MMA16816(o[2 * dd],     ph, b0h);
                MMA16816(o[2 * dd],     pl, b0h);
                MMA16816(o[2 * dd],     ph, b0l);
                MMA16816(o[2 * dd + 1], ph, b1h);
                MMA16816(o[2 * dd + 1], pl, b1h);
                MMA16816(o[2 * dd + 1], ph, b1l);
            }
        }
        __syncthreads();                 // all warps done reading V
        if (have_next) load_tile2(Vh, Vl, g_vh, g_vl, nx);   // prefetch V
        CP_COMMIT();

        tile = nx;
    }

    // ---- epilogue: normalize, bf16 hi/lo split to [S, H*D] ----
    const float i0 = 1.0f / l0, i1 = 1.0f / l1;
    const int s0 = t * 128 + wrow + g, s1 = s0 + 8;
#pragma unroll
    for (int j = 0; j < 16; j++) {
        int col = h * D_HEAD + 8 * j + 2 * tq;
        float v0 = o[j][0] * i0, v1 = o[j][1] * i0;
        uint32_t hv = pack_bf16x2(v0, v1);
        uint32_t lv = pack_bf16x2_res(v0, v1, hv);
        *(uint32_t*)(g_att_hi + (size_t)s0 * E_DIM + col) = hv;
        *(uint32_t*)(g_att_lo + (size_t)s0 * E_DIM + col) = lv;
        v0 = o[j][2] * i1; v1 = o[j][3] * i1;
        hv = pack_bf16x2(v0, v1);
        lv = pack_bf16x2_res(v0, v1, hv);
        *(uint32_t*)(g_att_hi + (size_t)s1 * E_DIM + col) = hv;
        *(uint32_t*)(g_att_lo + (size_t)s1 * E_DIM + col) = lv;
    }
}

// ---------------------------------------------------------------------------
extern "C" void kernel_launch(void* const* d_in, const int* in_sizes, int n_in,
                              void* d_out, int out_size)
{
    const float* x    = (const float*)d_in[0];
    const float* wq   = (const float*)d_in[1];
    const float* wk   = (const float*)d_in[2];
    const float* wv   = (const float*)d_in[3];
    const float* wo   = (const float*)d_in[4];
    const float* rope = (const float*)d_in[5];
    const int* anchors = (const int*)d_in[6];
    float* out = (float*)d_out;

    const int kanch = in_sizes[6] / (H_NUM * T_NUM);  // 8

    __nv_bfloat16 *xh, *xl, *qTh, *qTl, *kTh, *kTl, *vTh, *vTl, *oTh, *oTl;
    __nv_bfloat16 *qh, *ql, *kh, *kl, *vh, *vl, *ah, *al;
    cudaGetSymbolAddress((void**)&xh, g_x_hi);
    cudaGetSymbolAddress((void**)&xl, g_x_lo);
    cudaGetSymbolAddress((void**)&qTh, g_wqT_hi);
    cudaGetSymbolAddress((void**)&qTl, g_wqT_lo);
    cudaGetSymbolAddress((void**)&kTh, g_wkT_hi);
    cudaGetSymbolAddress((void**)&kTl, g_wkT_lo);
    cudaGetSymbolAddress((void**)&vTh, g_wvT_hi);
    cudaGetSymbolAddress((void**)&vTl, g_wvT_lo);
    cudaGetSymbolAddress((void**)&oTh, g_woT_hi);
    cudaGetSymbolAddress((void**)&oTl, g_woT_lo);
    cudaGetSymbolAddress((void**)&qh, g_qh);
    cudaGetSymbolAddress((void**)&ql, g_ql);
    cudaGetSymbolAddress((void**)&kh, g_kh);
    cudaGetSymbolAddress((void**)&kl, g_kl);
    cudaGetSymbolAddress((void**)&vh, g_vh);
    cudaGetSymbolAddress((void**)&vl, g_vl);
    cudaGetSymbolAddress((void**)&ah, g_att_hi);
    cudaGetSymbolAddress((void**)&al, g_att_lo);

    cudaFuncSetAttribute(gemm_mma, cudaFuncAttributeMaxDynamicSharedMemorySize, GEMM_SMEM);
    cudaFuncSetAttribute(attn_mma, cudaFuncAttributeMaxDynamicSharedMemorySize, ATT_SMEM);

    // 1. split x -> bf16 hi/lo
    split_kernel<<<(S_DIM * E_DIM / 4 + 255) / 256, 256>>>(x, xh, xl, S_DIM * E_DIM);

    // 2. transpose + split weights -> [N, K] bf16 hi/lo
    dim3 tgrid(E_DIM / 32, E_DIM / 32), tblk(32, 8);
    transpose_split_kernel<<<tgrid, tblk>>>(wq, qTh, qTl);
    transpose_split_kernel<<<tgrid, tblk>>>(wk, kTh, kTl);
    transpose_split_kernel<<<tgrid, tblk>>>(wv, vTh, vTl);
    transpose_split_kernel<<<tgrid, tblk>>>(wo, oTh, oTl);

    // 3. HMMA QKV projections -> bf16 hi/lo head-major (RoPE fused for Q,K)
    dim3 ggrid(E_DIM / 128, S_DIM / 128);  // (16, 32)
    gemm_mma<<<ggrid, 256, GEMM_SMEM>>>(xh, xl, qTh, qTl, nullptr, qh, ql, rope, 2);
    gemm_mma<<<ggrid, 256, GEMM_SMEM>>>(xh, xl, kTh, kTl, nullptr, kh, kl, rope, 2);
    gemm_mma<<<ggrid, 256, GEMM_SMEM>>>(xh, xl, vTh, vTl, nullptr, vh, vl, nullptr, 1);

    // 4. block-sparse attention (mma.sync bf16 splits) -> bf16 hi/lo att
    dim3 agrid(T_NUM, H_NUM);
    attn_mma<<<agrid, 256, ATT_SMEM>>>(anchors, kanch);

    // 5. out projection -> d_out
    gemm_mma<<<ggrid, 256, GEMM_SMEM>>>(ah, al, oTh, oTl, out, nullptr, nullptr, nullptr, 0);
}

// round 5
// speedup vs baseline: 3.1290x; 1.1246x over previous
#include <cuda_runtime.h>
#include <cuda_bf16.h>
#include <math.h>
#include <stdint.h>

#define S_DIM 4096
#define E_DIM 2048
#define H_NUM 16
#define D_HEAD 128
#define T_NUM 32

// ---------------------------------------------------------------------------
// Scratch (__device__ globals; allocation-free rule)
// ---------------------------------------------------------------------------
__device__ __nv_bfloat16 g_x_hi[S_DIM * E_DIM];
__device__ __nv_bfloat16 g_x_lo[S_DIM * E_DIM];
__device__ __nv_bfloat16 g_wqT_hi[E_DIM * E_DIM];
__device__ __nv_bfloat16 g_wqT_lo[E_DIM * E_DIM];
__device__ __nv_bfloat16 g_wkT_hi[E_DIM * E_DIM];
__device__ __nv_bfloat16 g_wkT_lo[E_DIM * E_DIM];
__device__ __nv_bfloat16 g_wvT_hi[E_DIM * E_DIM];
__device__ __nv_bfloat16 g_wvT_lo[E_DIM * E_DIM];
__device__ __nv_bfloat16 g_woT_hi[E_DIM * E_DIM];
__device__ __nv_bfloat16 g_woT_lo[E_DIM * E_DIM];
// head-major bf16 hi/lo QKV (RoPE already applied to Q,K)
__device__ __nv_bfloat16 g_qh[H_NUM * S_DIM * D_HEAD];
__device__ __nv_bfloat16 g_ql[H_NUM * S_DIM * D_HEAD];
__device__ __nv_bfloat16 g_kh[H_NUM * S_DIM * D_HEAD];
__device__ __nv_bfloat16 g_kl[H_NUM * S_DIM * D_HEAD];
__device__ __nv_bfloat16 g_vh[H_NUM * S_DIM * D_HEAD];
__device__ __nv_bfloat16 g_vl[H_NUM * S_DIM * D_HEAD];
__device__ __nv_bfloat16 g_att_hi[S_DIM * E_DIM];
__device__ __nv_bfloat16 g_att_lo[S_DIM * E_DIM];

// ---------------------------------------------------------------------------
// base-ISA PTX helpers (compute_103 virtual arch: no tcgen05/TMA)
// ---------------------------------------------------------------------------
__device__ __forceinline__ uint32_t smem_u32(const void* p) {
    uint32_t a;
    asm("{ .reg .u64 t; cvta.to.shared.u64 t, %1; cvt.u32.u64 %0, t; }" : "=r"(a) : "l"(p));
    return a;
}

#define CP_ASYNC16(dst, src) \
    asm volatile("cp.async.cg.shared.global [%0], [%1], 16;" :: "r"(dst), "l"(src))
#define CP_COMMIT() asm volatile("cp.async.commit_group;" ::: "memory")
#define CP_WAIT1() asm volatile("cp.async.wait_group 1;" ::: "memory")
#define CP_WAIT0() asm volatile("cp.async.wait_group 0;" ::: "memory")

#define LDSM4(r0, r1, r2, r3, addr) \
    asm volatile("ldmatrix.sync.aligned.m8n8.x4.shared.b16 {%0,%1,%2,%3}, [%4];" \
        : "=r"(r0), "=r"(r1), "=r"(r2), "=r"(r3) : "r"(addr))
#define LDSM4T(r0, r1, r2, r3, addr) \
    asm volatile("ldmatrix.sync.aligned.m8n8.x4.trans.shared.b16 {%0,%1,%2,%3}, [%4];" \
        : "=r"(r0), "=r"(r1), "=r"(r2), "=r"(r3) : "r"(addr))

#define MMA16816(d, a, b) \
    asm volatile("mma.sync.aligned.m16n8k16.row.col.f32.bf16.bf16.f32 " \
        "{%0,%1,%2,%3}, {%4,%5,%6,%7}, {%8,%9}, {%0,%1,%2,%3};" \
        : "+f"((d)[0]), "+f"((d)[1]), "+f"((d)[2]), "+f"((d)[3]) \
        : "r"((a)[0]), "r"((a)[1]), "r"((a)[2]), "r"((a)[3]), \
          "r"((b)[0]), "r"((b)[1]))

__device__ __forceinline__ uint32_t pack_bf16x2(float a, float b) {
    __nv_bfloat162 v = __float22bfloat162_rn(make_float2(a, b));
    return *(uint32_t*)&v;
}
__device__ __forceinline__ uint32_t pack_bf16x2_res(float a, float b, uint32_t hibits) {
    __nv_bfloat162 h = *(__nv_bfloat162*)&hibits;
    return pack_bf16x2(a - __bfloat162float(h.x), b - __bfloat162float(h.y));
}

// ---------------------------------------------------------------------------
// fp32 -> bf16 hi/lo split (element-wise)
// ---------------------------------------------------------------------------
__global__ void split_kernel(const float* __restrict__ in,
                             __nv_bfloat16* __restrict__ hi,
                             __nv_bfloat16* __restrict__ lo, int n)
{
    int i = (blockIdx.x * blockDim.x + threadIdx.x) * 4;
    if (i >= n) return;
    float4 v = *(const float4*)(in + i);
    __nv_bfloat16 h0 = __float2bfloat16(v.x), h1 = __float2bfloat16(v.y);
    __nv_bfloat16 h2 = __float2bfloat16(v.z), h3 = __float2bfloat16(v.w);
    __nv_bfloat162 hA, hB, lA, lB;
    hA.x = h0; hA.y = h1; hB.x = h2; hB.y = h3;
    lA.x = __float2bfloat16(v.x - __bfloat162float(h0));
    lA.y = __float2bfloat16(v.y - __bfloat162float(h1));
    lB.x = __float2bfloat16(v.z - __bfloat162float(h2));
    lB.y = __float2bfloat16(v.w - __bfloat162float(h3));
    *(__nv_bfloat162*)(hi + i) = hA;
    *(__nv_bfloat162*)(hi + i + 2) = hB;
    *(__nv_bfloat162*)(lo + i) = lA;
    *(__nv_bfloat162*)(lo + i + 2) = lB;
}

// ---------------------------------------------------------------------------
// fused transpose+split of all 4 weight matrices: w[K,N] -> wT[N,K] hi/lo
// ---------------------------------------------------------------------------
__global__ void transpose_split4(const float* __restrict__ wq, const float* __restrict__ wk,
                                 const float* __restrict__ wv, const float* __restrict__ wo)
{
    __shared__ float tile[32][33];
    const float* w;
    __nv_bfloat16 *hiT, *loT;
    switch (blockIdx.z) {
        case 0:  w = wq; hiT = g_wqT_hi; loT = g_wqT_lo; break;
        case 1:  w = wk; hiT = g_wkT_hi; loT = g_wkT_lo; break;
        case 2:  w = wv; hiT = g_wvT_hi; loT = g_wvT_lo; break;
        default: w = wo; hiT = g_woT_hi; loT = g_woT_lo; break;
    }
    int n = blockIdx.x * 32 + threadIdx.x;
    int k0 = blockIdx.y * 32;
#pragma unroll
    for (int j = 0; j < 32; j += 8)
        tile[threadIdx.y + j][threadIdx.x] = w[(k0 + threadIdx.y + j) * E_DIM + n];
    __syncthreads();
#pragma unroll
    for (int j = 0; j < 32; j += 8) {
        int orow = blockIdx.x * 32 + threadIdx.y + j;
        int ocol = k0 + threadIdx.x;
        float v = tile[threadIdx.x][threadIdx.y + j];
        __nv_bfloat16 h = __float2bfloat16(v);
        hiT[orow * E_DIM + ocol] = h;
        loT[orow * E_DIM + ocol] = __float2bfloat16(v - __bfloat162float(h));
    }
}

// ---------------------------------------------------------------------------
// HMMA split-bf16 GEMM (CTA 128x128, K-chunk 64, cp.async double buffer)
// mode 0: fp32 row-major out[M,2048]
// mode 3: fused QKV — blockIdx.x = which*16 + nb; B/out from device globals,
//         RoPE for Q,K; bf16 hi/lo head-major outputs
// ---------------------------------------------------------------------------
#define ROW_B 144
#define TILE_B (128 * ROW_B)
#define STAGE_B (4 * TILE_B)
#define GEMM_SMEM (2 * STAGE_B)

__global__ __launch_bounds__(256, 1)
void gemm_mma(const __nv_bfloat16* __restrict__ Ahi, const __nv_bfloat16* __restrict__ Alo,
              const __nv_bfloat16* __restrict__ Bhi, const __nv_bfloat16* __restrict__ Blo,
              float* __restrict__ outf,
              __nv_bfloat16* __restrict__ outh, __nv_bfloat16* __restrict__ outl,
              const float* __restrict__ rope, int mode)
{
    extern __shared__ char smem[];
    const uint32_t smem_base = smem_u32(smem);
    const int tid = threadIdx.x;
    const int wid = tid >> 5;
    const int lane = tid & 31;
    const int m0 = blockIdx.y * 128;
    const int wM = wid >> 2;
    const int wN = wid & 3;

    const __nv_bfloat16 *bh_p, *bl_p;
    __nv_bfloat16 *oh_p = nullptr, *ol_p = nullptr;
    bool do_rope = false;
    int n0, hsel;
    if (mode == 3) {
        int which = blockIdx.x >> 4;
        int nb = blockIdx.x & 15;
        n0 = nb * 128; hsel = nb;
        if (which == 0)      { bh_p = g_wqT_hi; bl_p = g_wqT_lo; oh_p = g_qh; ol_p = g_ql; do_rope = true; }
        else if (which == 1) { bh_p = g_wkT_hi; bl_p = g_wkT_lo; oh_p = g_kh; ol_p = g_kl; do_rope = true; }
        else                 { bh_p = g_wvT_hi; bl_p = g_wvT_lo; oh_p = g_vh; ol_p = g_vl; }
    } else {
        n0 = blockIdx.x * 128; hsel = blockIdx.x;
        bh_p = Bhi; bl_p = Blo; oh_p = outh; ol_p = outl;
    }

    const char* srcs[4] = {
        (const char*)(Ahi + (size_t)m0 * E_DIM),
        (const char*)(Alo + (size_t)m0 * E_DIM),
        (const char*)(bh_p + (size_t)n0 * E_DIM),
        (const char*)(bl_p + (size_t)n0 * E_DIM)
    };

    auto issue_chunk = [&](int c, int p) {
        uint32_t sb = smem_base + p * STAGE_B;
#pragma unroll
        for (int t = 0; t < 4; t++) {
#pragma unroll
            for (int i = 0; i < 4; i++) {
                int idx = tid + i * 256;
                int row = idx >> 3;
                int c16 = idx & 7;
                uint32_t dst = sb + t * TILE_B + row * ROW_B + c16 * 16;
                const char* src = srcs[t] + (size_t)row * 4096 + c * 128 + c16 * 16;
                CP_ASYNC16(dst, src);
            }
        }
    };

    float acc[4][4][4];
#pragma unroll
    for (int mt = 0; mt < 4; mt++)
#pragma unroll
        for (int nt = 0; nt < 4; nt++)
#pragma unroll
            for (int e = 0; e < 4; e++) acc[mt][nt][e] = 0.0f;

    const int a_row = (lane & 15);
    const int a_kb = (lane >> 4) * 16;
    const int b_nrow = (lane & 7) | ((lane & 16) >> 1);
    const int b_kb = (lane & 8) ? 16 : 0;

    issue_chunk(0, 0);
    CP_COMMIT();

    for (int c = 0; c < 32; c++) {
        if (c + 1 < 32) {
            issue_chunk(c + 1, (c + 1) & 1);
            CP_COMMIT();
            CP_WAIT1();
        } else {
            CP_WAIT0();
        }
        __syncthreads();

        uint32_t sb = smem_base + (c & 1) * STAGE_B;
        uint32_t aH = sb + (wM * 64 + a_row) * ROW_B + a_kb;
        uint32_t aL = aH + TILE_B;
        uint32_t bH = sb + 2 * TILE_B + (wN * 32 + b_nrow) * ROW_B + b_kb;
        uint32_t bL = bH + TILE_B;

#pragma unroll
        for (int ks = 0; ks < 4; ks++) {
            uint32_t ah[4][4], al[4][4], bh[4][2], bl[4][2];
#pragma unroll
            for (int mt = 0; mt < 4; mt++) {
                LDSM4(ah[mt][0], ah[mt][1], ah[mt][2], ah[mt][3],
                      aH + mt * (16 * ROW_B) + ks * 32);
                LDSM4(al[mt][0], al[mt][1], al[mt][2], al[mt][3],
                      aL + mt * (16 * ROW_B) + ks * 32);
            }
#pragma unroll
            for (int bt = 0; bt < 2; bt++) {
                LDSM4(bh[bt * 2][0], bh[bt * 2][1], bh[bt * 2 + 1][0], bh[bt * 2 + 1][1],
                      bH + bt * (16 * ROW_B) + ks * 32);
                LDSM4(bl[bt * 2][0], bl[bt * 2][1], bl[bt * 2 + 1][0], bl[bt * 2 + 1][1],
                      bL + bt * (16 * ROW_B) + ks * 32);
            }
#pragma unroll
            for (int mt = 0; mt < 4; mt++)
#pragma unroll
                for (int nt = 0; nt < 4; nt++) {
                    MMA16816(acc[mt][nt], ah[mt], bh[nt]);
                    MMA16816(acc[mt][nt], ah[mt], bl[nt]);
                    MMA16816(acc[mt][nt], al[mt], bh[nt]);
                }
        }
        __syncthreads();
    }

    // epilogue through smem so RoPE pairs d/d+64 are thread-local
    float* csm = (float*)smem;     // [128][132]
    const int g = lane >> 2;
    const int tg = lane & 3;
#pragma unroll
    for (int mt = 0; mt < 4; mt++)
#pragma unroll
        for (int nt = 0; nt < 4; nt++) {
            int r = wM * 64 + mt * 16 + g;
            int col = wN * 32 + nt * 8 + tg * 2;
            csm[r * 132 + col]           = acc[mt][nt][0];
            csm[r * 132 + col + 1]       = acc[mt][nt][1];
            csm[(r + 8) * 132 + col]     = acc[mt][nt][2];
            csm[(r + 8) * 132 + col + 1] = acc[mt][nt][3];
        }
    __syncthreads();

#pragma unroll 4
    for (int it = 0; it < 32; it++) {
        int idx = tid + it * 256;
        int row = idx >> 6;
        int d = idx & 63;
        float lo = csm[row * 132 + d];
        float hi = csm[row * 132 + d + 64];
        int s = m0 + row;
        if (mode == 0) {
            float* orow = outf + (size_t)s * E_DIM + n0;
            orow[d] = lo;
            orow[d + 64] = hi;
        } else {
            if (do_rope) {
                float ang = rope[s * (D_HEAD / 2) + d];
                float sn, cs;
                __sincosf(ang, &sn, &cs);
                float nlo = lo * cs - hi * sn;
                float nhi = hi * cs + lo * sn;
                lo = nlo; hi = nhi;
            }
            size_t base = ((size_t)hsel * S_DIM + s) * D_HEAD;
            __nv_bfloat16 hl = __float2bfloat16(lo);
            __nv_bfloat16 hh = __float2bfloat16(hi);
            oh_p[base + d]      = hl;
            oh_p[base + d + 64] = hh;
            ol_p[base + d]      = __float2bfloat16(lo - __bfloat162float(hl));
            ol_p[base + d + 64] = __float2bfloat16(hi - __bfloat162float(hh));
        }
    }
}

// ---------------------------------------------------------------------------
// Block-sparse attention on mma.sync bf16 (FA2-style), CTA per (q-tile, head).
// Fully-masked anchor tiles (a > t) are skipped — exact (reference weights 0).
// ---------------------------------------------------------------------------
#define NEG_BIG (-1e10f)
#define ATT_TILE 32768
#define ATT_SMEM (6 * ATT_TILE)   // 196608

__global__ __launch_bounds__(256, 1)
void attn_mma(const int* __restrict__ anchors, int kanch)
{
    extern __shared__ char smn[];
    __shared__ int s_tiles[16];
    __shared__ int s_cnt;
    const uint32_t base = smem_u32(smn);
    const uint32_t Qh = base,            Ql = base + ATT_TILE;
    const uint32_t Kh = base + 2*ATT_TILE, Kl = base + 3*ATT_TILE;
    const uint32_t Vh = base + 4*ATT_TILE, Vl = base + 5*ATT_TILE;

    const int t = blockIdx.x, h = blockIdx.y;
    const int tid = threadIdx.x;
    const int w = tid >> 5, lane = tid & 31;
    const int g = lane >> 2, tq = lane & 3;
    const float scale = 0.088388347648318447f;

    // build filtered tile list: anchors <= t (duplicates kept), then local t
    const int abase = (h * T_NUM + t) * kanch;
    if (tid == 0) {
        int n = 0;
        for (int i = 0; i < kanch; i++) {
            int a = anchors[abase + i];
            if (a <= t) s_tiles[n++] = a;
        }
        s_tiles[n++] = t;
        s_cnt = n;
    }
    __syncthreads();
    const int cnt = s_cnt;
    int tile = s_tiles[0];

    auto load_tile2 = [&](uint32_t dh, uint32_t dl,
                          const __nv_bfloat16* sh, const __nv_bfloat16* sl, int tl) {
        const char* ph = (const char*)(sh + ((size_t)h * S_DIM + (size_t)tl * 128) * D_HEAD);
        const char* pl = (const char*)(sl + ((size_t)h * S_DIM + (size_t)tl * 128) * D_HEAD);
        for (int i = tid; i < 2048; i += 256) {
            int row = i >> 4, c16 = i & 15;
            uint32_t off = row * 256 + ((c16 ^ (row & 7)) << 4);
            CP_ASYNC16(dh + off, ph + (size_t)row * 256 + c16 * 16);
            CP_ASYNC16(dl + off, pl + (size_t)row * 256 + c16 * 16);
        }
    };

    // group0: Q + K0 ; group1: V0
    load_tile2(Qh, Ql, g_qh, g_ql, t);
    load_tile2(Kh, Kl, g_kh, g_kl, tile);
    CP_COMMIT();
    load_tile2(Vh, Vl, g_vh, g_vl, tile);
    CP_COMMIT();

    float o[16][4];
#pragma unroll
    for (int j = 0; j < 16; j++)
#pragma unroll
        for (int e = 0; e < 4; e++) o[j][e] = 0.0f;
    float m0 = -1e30f, m1 = -1e30f, l0 = 0.0f, l1 = 0.0f;

    const int wrow = w * 16;
    const int arow = wrow + (lane & 15);
    const int asw = arow & 7;
    const int ahc = lane >> 4;
    const int bnr = (lane & 7) | ((lane & 16) >> 1);
    const int bhc = (lane & 8) >> 3;
    const int vrl = lane & 15;
    const int vhc = lane >> 4;

    for (int it = 0; it < cnt; it++) {
        const bool have_next = (it + 1 < cnt);
        const int nx = have_next ? s_tiles[it + 1] : 0;

        CP_WAIT1();          // K_it (and Q on it==0) ready
        __syncthreads();

        // ---- S = Q K^T (3 split terms) ----
        float s[16][4];
#pragma unroll
        for (int j = 0; j < 16; j++)
#pragma unroll
            for (int e = 0; e < 4; e++) s[j][e] = 0.0f;

#pragma unroll
        for (int ks = 0; ks < 8; ks++) {
            uint32_t qh4[4], ql4[4];
            uint32_t aoff = arow * 256 + (((ks * 2 + ahc) ^ asw) << 4);
            LDSM4(qh4[0], qh4[1], qh4[2], qh4[3], Qh + aoff);
            LDSM4(ql4[0], ql4[1], ql4[2], ql4[3], Ql + aoff);
#pragma unroll
            for (int nb = 0; nb < 8; nb++) {
                int br = nb * 16 + bnr;
                uint32_t boff = br * 256 + (((ks * 2 + bhc) ^ (br & 7)) << 4);
                uint32_t kh4[4], kl4[4];
                LDSM4(kh4[0], kh4[1], kh4[2], kh4[3], Kh + boff);
                LDSM4(kl4[0], kl4[1], kl4[2], kl4[3], Kl + boff);
                uint32_t b0h[2] = {kh4[0], kh4[1]}, b1h[2] = {kh4[2], kh4[3]};
                uint32_t b0l[2] = {kl4[0], kl4[1]}, b1l[2] = {kl4[2], kl4[3]};
                MMA16816(s[2 * nb],     qh4, b0h);
                MMA16816(s[2 * nb],     qh4, b0l);
                MMA16816(s[2 * nb],     ql4, b0h);
                MMA16816(s[2 * nb + 1], qh4, b1h);
                MMA16816(s[2 * nb + 1], qh4, b1l);
                MMA16816(s[2 * nb + 1], ql4, b1h);
            }
        }
        __syncthreads();                 // all warps done reading K
        if (have_next) load_tile2(Kh, Kl, g_kh, g_kl, nx);
        CP_COMMIT();

        // ---- mask + online softmax (quad shuffles only) ----
        const int qp0 = t * 128 + wrow + g;
        const int qp1 = qp0 + 8;
        const int kb = tile * 128 + 2 * tq;
        float mx0 = -1e30f, mx1 = -1e30f;
#pragma unroll
        for (int j = 0; j < 16; j++) {
            int kc = kb + 8 * j;
            s[j][0] = (kc     > qp0) ? NEG_BIG : s[j][0] * scale;
            s[j][1] = (kc + 1 > qp0) ? NEG_BIG : s[j][1] * scale;
            s[j][2] = (kc     > qp1) ? NEG_BIG : s[j][2] * scale;
            s[j][3] = (kc + 1 > qp1) ? NEG_BIG : s[j][3] * scale;
            mx0 = fmaxf(mx0, fmaxf(s[j][0], s[j][1]));
            mx1 = fmaxf(mx1, fmaxf(s[j][2], s[j][3]));
        }
        mx0 = fmaxf(mx0, __shfl_xor_sync(0xffffffffu, mx0, 1));
        mx0 = fmaxf(mx0, __shfl_xor_sync(0xffffffffu, mx0, 2));
        mx1 = fmaxf(mx1, __shfl_xor_sync(0xffffffffu, mx1, 1));
        mx1 = fmaxf(mx1, __shfl_xor_sync(0xffffffffu, mx1, 2));
        const float mn0 = fmaxf(m0, mx0), mn1 = fmaxf(m1, mx1);
        const float f0 = __expf(m0 - mn0), f1 = __expf(m1 - mn1);
        float ls0 = 0.0f, ls1 = 0.0f;
#pragma unroll
        for (int j = 0; j < 16; j++) {
            s[j][0] = __expf(s[j][0] - mn0);
            s[j][1] = __expf(s[j][1] - mn0);
            s[j][2] = __expf(s[j][2] - mn1);
            s[j][3] = __expf(s[j][3] - mn1);
            ls0 += s[j][0] + s[j][1];
            ls1 += s[j][2] + s[j][3];
        }
        ls0 += __shfl_xor_sync(0xffffffffu, ls0, 1);
        ls0 += __shfl_xor_sync(0xffffffffu, ls0, 2);
        ls1 += __shfl_xor_sync(0xffffffffu, ls1, 1);
        ls1 += __shfl_xor_sync(0xffffffffu, ls1, 2);
        l0 = l0 * f0 + ls0; l1 = l1 * f1 + ls1;
        m0 = mn0; m1 = mn1;
#pragma unroll
        for (int j = 0; j < 16; j++) {
            o[j][0] *= f0; o[j][1] *= f0;
            o[j][2] *= f1; o[j][3] *= f1;
        }

        CP_WAIT1();          // V_it ready
        __syncthreads();

        // ---- O += P V (3 split terms), P packed from S fragments ----
#pragma unroll
        for (int ks = 0; ks < 8; ks++) {
            uint32_t ph[4], pl[4];
            ph[0] = pack_bf16x2(s[2 * ks][0], s[2 * ks][1]);
            ph[1] = pack_bf16x2(s[2 * ks][2], s[2 * ks][3]);
            ph[2] = pack_bf16x2(s[2 * ks + 1][0], s[2 * ks + 1][1]);
            ph[3] = pack_bf16x2(s[2 * ks + 1][2], s[2 * ks + 1][3]);
            pl[0] = pack_bf16x2_res(s[2 * ks][0], s[2 * ks][1], ph[0]);
            pl[1] = pack_bf16x2_res(s[2 * ks][2], s[2 * ks][3], ph[1]);
            pl[2] = pack_bf16x2_res(s[2 * ks + 1][0], s[2 * ks + 1][1], ph[2]);
            pl[3] = pack_bf16x2_res(s[2 * ks + 1][2], s[2 * ks + 1][3], ph[3]);
            int vr = ks * 16 + vrl;
#pragma unroll
            for (int dd = 0; dd < 8; dd++) {
                uint32_t voff = vr * 256 + (((dd * 2 + vhc) ^ (vr & 7)) << 4);
                uint32_t vh4[4], vl4[4];
                LDSM4T(vh4[0], vh4[1], vh4[2], vh4[3], Vh + voff);
                LDSM4T(vl4[0], vl4[1], vl4[2], vl4[3], Vl + voff);
                uint32_t b0h[2] = {vh4[0], vh4[1]}, b1h[2] = {vh4[2], vh4[3]};
                uint32_t b0l[2] = {vl4[0], vl4[1]}, b1l[2] = {vl4[2], vl4[3]};
                MMA16816(o[2 * dd],     ph, b0h);
                MMA16816(o[2 * dd],     pl, b0h);
                MMA16816(o[2 * dd],     ph, b0l);
                MMA16816(o[2 * dd + 1], ph, b1h);
                MMA16816(o[2 * dd + 1], pl, b1h);
                MMA16816(o[2 * dd + 1], ph, b1l);
            }
        }
        __syncthreads();                 // all warps done reading V
        if (have_next) load_tile2(Vh, Vl, g_vh, g_vl, nx);
        CP_COMMIT();

        tile = nx;
    }

    // ---- epilogue: normalize, bf16 hi/lo split to [S, H*D] ----
    const float i0 = 1.0f / l0, i1 = 1.0f / l1;
    const int s0 = t * 128 + wrow + g, s1 = s0 + 8;
#pragma unroll
    for (int j = 0; j < 16; j++) {
        int col = h * D_HEAD + 8 * j + 2 * tq;
        float v0 = o[j][0] * i0, v1 = o[j][1] * i0;
        uint32_t hv = pack_bf16x2(v0, v1);
        uint32_t lv = pack_bf16x2_res(v0, v1, hv);
        *(uint32_t*)(g_att_hi + (size_t)s0 * E_DIM + col) = hv;
        *(uint32_t*)(g_att_lo + (size_t)s0 * E_DIM + col) = lv;
        v0 = o[j][2] * i1; v1 = o[j][3] * i1;
        hv = pack_bf16x2(v0, v1);
        lv = pack_bf16x2_res(v0, v1, hv);
        *(uint32_t*)(g_att_hi + (size_t)s1 * E_DIM + col) = hv;
        *(uint32_t*)(g_att_lo + (size_t)s1 * E_DIM + col) = lv;
    }
}

// ---------------------------------------------------------------------------
extern "C" void kernel_launch(void* const* d_in, const int* in_sizes, int n_in,
                              void* d_out, int out_size)
{
    const float* x    = (const float*)d_in[0];
    const float* wq   = (const float*)d_in[1];
    const float* wk   = (const float*)d_in[2];
    const float* wv   = (const float*)d_in[3];
    const float* wo   = (const float*)d_in[4];
    const float* rope = (const float*)d_in[5];
    const int* anchors = (const int*)d_in[6];
    float* out = (float*)d_out;

    const int kanch = in_sizes[6] / (H_NUM * T_NUM);  // 8

    __nv_bfloat16 *xh, *xl, *oTh, *oTl, *ah, *al;
    cudaGetSymbolAddress((void**)&xh, g_x_hi);
    cudaGetSymbolAddress((void**)&xl, g_x_lo);
    cudaGetSymbolAddress((void**)&oTh, g_woT_hi);
    cudaGetSymbolAddress((void**)&oTl, g_woT_lo);
    cudaGetSymbolAddress((void**)&ah, g_att_hi);
    cudaGetSymbolAddress((void**)&al, g_att_lo);

    cudaFuncSetAttribute(gemm_mma, cudaFuncAttributeMaxDynamicSharedMemorySize, GEMM_SMEM);
    cudaFuncSetAttribute(attn_mma, cudaFuncAttributeMaxDynamicSharedMemorySize, ATT_SMEM);

    // 1. split x -> bf16 hi/lo
    split_kernel<<<(S_DIM * E_DIM / 4 + 255) / 256, 256>>>(x, xh, xl, S_DIM * E_DIM);

    // 2. fused transpose+split of all weights
    dim3 tgrid(E_DIM / 32, E_DIM / 32, 4), tblk(32, 8);
    transpose_split4<<<tgrid, tblk>>>(wq, wk, wv, wo);

    // 3. fused QKV projection (RoPE inside), bf16 hi/lo head-major
    dim3 qkvgrid(48, S_DIM / 128);  // (48, 32)
    gemm_mma<<<qkvgrid, 256, GEMM_SMEM>>>(xh, xl, nullptr, nullptr,
                                          nullptr, nullptr, nullptr, rope, 3);

    // 4. block-sparse attention (skips fully-masked tiles)
    dim3 agrid(T_NUM, H_NUM);
    attn_mma<<<agrid, 256, ATT_SMEM>>>(anchors, kanch);

    // 5. out projection -> d_out   (5th launch: ncu profiles this one)
    dim3 ogrid(E_DIM / 128, S_DIM / 128);
    gemm_mma<<<ogrid, 256, GEMM_SMEM>>>(ah, al, oTh, oTl, out, nullptr, nullptr,
                                        nullptr, 0);
}

// round 6
// speedup vs baseline: 3.1720x; 1.0137x over previous
#include <cuda_runtime.h>
#include <cuda_bf16.h>
#include <math.h>
#include <stdint.h>

#define S_DIM 4096
#define E_DIM 2048
#define H_NUM 16
#define D_HEAD 128
#define T_NUM 32

// ---------------------------------------------------------------------------
// Scratch (__device__ globals; allocation-free rule)
// ---------------------------------------------------------------------------
__device__ __nv_bfloat16 g_x_hi[S_DIM * E_DIM];
__device__ __nv_bfloat16 g_x_lo[S_DIM * E_DIM];
__device__ __nv_bfloat16 g_wqT_hi[E_DIM * E_DIM];
__device__ __nv_bfloat16 g_wqT_lo[E_DIM * E_DIM];
__device__ __nv_bfloat16 g_wkT_hi[E_DIM * E_DIM];
__device__ __nv_bfloat16 g_wkT_lo[E_DIM * E_DIM];
__device__ __nv_bfloat16 g_wvT_hi[E_DIM * E_DIM];
__device__ __nv_bfloat16 g_wvT_lo[E_DIM * E_DIM];
__device__ __nv_bfloat16 g_woT_hi[E_DIM * E_DIM];
__device__ __nv_bfloat16 g_woT_lo[E_DIM * E_DIM];
// head-major bf16 hi/lo QKV (RoPE already applied to Q,K)
__device__ __nv_bfloat16 g_qh[H_NUM * S_DIM * D_HEAD];
__device__ __nv_bfloat16 g_ql[H_NUM * S_DIM * D_HEAD];
__device__ __nv_bfloat16 g_kh[H_NUM * S_DIM * D_HEAD];
__device__ __nv_bfloat16 g_kl[H_NUM * S_DIM * D_HEAD];
__device__ __nv_bfloat16 g_vh[H_NUM * S_DIM * D_HEAD];
__device__ __nv_bfloat16 g_vl[H_NUM * S_DIM * D_HEAD];
__device__ __nv_bfloat16 g_att_hi[S_DIM * E_DIM];
__device__ __nv_bfloat16 g_att_lo[S_DIM * E_DIM];

// ---------------------------------------------------------------------------
// base-ISA PTX helpers (compute_103 virtual arch: no tcgen05/TMA)
// ---------------------------------------------------------------------------
__device__ __forceinline__ uint32_t smem_u32(const void* p) {
    uint32_t a;
    asm("{ .reg .u64 t; cvta.to.shared.u64 t, %1; cvt.u32.u64 %0, t; }" : "=r"(a) : "l"(p));
    return a;
}

#define CP_ASYNC16(dst, src) \
    asm volatile("cp.async.cg.shared.global [%0], [%1], 16;" :: "r"(dst), "l"(src))
#define CP_COMMIT() asm volatile("cp.async.commit_group;" ::: "memory")
#define CP_WAIT1() asm volatile("cp.async.wait_group 1;" ::: "memory")
#define CP_WAIT0() asm volatile("cp.async.wait_group 0;" ::: "memory")

#define LDSM4(r0, r1, r2, r3, addr) \
    asm volatile("ldmatrix.sync.aligned.m8n8.x4.shared.b16 {%0,%1,%2,%3}, [%4];" \
        : "=r"(r0), "=r"(r1), "=r"(r2), "=r"(r3) : "r"(addr))
#define LDSM4T(r0, r1, r2, r3, addr) \
    asm volatile("ldmatrix.sync.aligned.m8n8.x4.trans.shared.b16 {%0,%1,%2,%3}, [%4];" \
        : "=r"(r0), "=r"(r1), "=r"(r2), "=r"(r3) : "r"(addr))

#define MMA16816(d, a, b) \
    asm volatile("mma.sync.aligned.m16n8k16.row.col.f32.bf16.bf16.f32 " \
        "{%0,%1,%2,%3}, {%4,%5,%6,%7}, {%8,%9}, {%0,%1,%2,%3};" \
        : "+f"((d)[0]), "+f"((d)[1]), "+f"((d)[2]), "+f"((d)[3]) \
        : "r"((a)[0]), "r"((a)[1]), "r"((a)[2]), "r"((a)[3]), \
          "r"((b)[0]), "r"((b)[1]))

__device__ __forceinline__ uint32_t pack_bf16x2(float a, float b) {
    __nv_bfloat162 v = __float22bfloat162_rn(make_float2(a, b));
    return *(uint32_t*)&v;
}
__device__ __forceinline__ uint32_t pack_bf16x2_res(float a, float b, uint32_t hibits) {
    __nv_bfloat162 h = *(__nv_bfloat162*)&hibits;
    return pack_bf16x2(a - __bfloat162float(h.x), b - __bfloat162float(h.y));
}

// ---------------------------------------------------------------------------
// fp32 -> bf16 hi/lo split (element-wise)
// ---------------------------------------------------------------------------
__global__ void split_kernel(const float* __restrict__ in,
                             __nv_bfloat16* __restrict__ hi,
                             __nv_bfloat16* __restrict__ lo, int n)
{
    int i = (blockIdx.x * blockDim.x + threadIdx.x) * 4;
    if (i >= n) return;
    float4 v = *(const float4*)(in + i);
    __nv_bfloat16 h0 = __float2bfloat16(v.x), h1 = __float2bfloat16(v.y);
    __nv_bfloat16 h2 = __float2bfloat16(v.z), h3 = __float2bfloat16(v.w);
    __nv_bfloat162 hA, hB, lA, lB;
    hA.x = h0; hA.y = h1; hB.x = h2; hB.y = h3;
    lA.x = __float2bfloat16(v.x - __bfloat162float(h0));
    lA.y = __float2bfloat16(v.y - __bfloat162float(h1));
    lB.x = __float2bfloat16(v.z - __bfloat162float(h2));
    lB.y = __float2bfloat16(v.w - __bfloat162float(h3));
    *(__nv_bfloat162*)(hi + i) = hA;
    *(__nv_bfloat162*)(hi + i + 2) = hB;
    *(__nv_bfloat162*)(lo + i) = lA;
    *(__nv_bfloat162*)(lo + i + 2) = lB;
}

// ---------------------------------------------------------------------------
// fused transpose+split of all 4 weight matrices: w[K,N] -> wT[N,K] hi/lo
// ---------------------------------------------------------------------------
__global__ void transpose_split4(const float* __restrict__ wq, const float* __restrict__ wk,
                                 const float* __restrict__ wv, const float* __restrict__ wo)
{
    __shared__ float tile[32][33];
    const float* w;
    __nv_bfloat16 *hiT, *loT;
    switch (blockIdx.z) {
        case 0:  w = wq; hiT = g_wqT_hi; loT = g_wqT_lo; break;
        case 1:  w = wk; hiT = g_wkT_hi; loT = g_wkT_lo; break;
        case 2:  w = wv; hiT = g_wvT_hi; loT = g_wvT_lo; break;
        default: w = wo; hiT = g_woT_hi; loT = g_woT_lo; break;
    }
    int n = blockIdx.x * 32 + threadIdx.x;
    int k0 = blockIdx.y * 32;
#pragma unroll
    for (int j = 0; j < 32; j += 8)
        tile[threadIdx.y + j][threadIdx.x] = w[(k0 + threadIdx.y + j) * E_DIM + n];
    __syncthreads();
#pragma unroll
    for (int j = 0; j < 32; j += 8) {
        int orow = blockIdx.x * 32 + threadIdx.y + j;
        int ocol = k0 + threadIdx.x;
        float v = tile[threadIdx.x][threadIdx.y + j];
        __nv_bfloat16 h = __float2bfloat16(v);
        hiT[orow * E_DIM + ocol] = h;
        loT[orow * E_DIM + ocol] = __float2bfloat16(v - __bfloat162float(h));
    }
}

// ---------------------------------------------------------------------------
// HMMA split-bf16 GEMM — CTA tile 256x128, 512 threads (16 warps, 4M x 4N),
// K-chunk 64, cp.async double buffer. 4 warps/SMSP to hide LDSM/MMA latency.
// mode 0: fp32 row-major out[M,2048]
// mode 3: fused QKV — blockIdx.x = which*16 + nb; RoPE for Q,K;
//         bf16 hi/lo head-major outputs
// ---------------------------------------------------------------------------
#define ROW_B 144
#define A_TILE_B (256 * ROW_B)       // 36864
#define B_TILE_B (128 * ROW_B)       // 18432
#define STAGE_B (2 * A_TILE_B + 2 * B_TILE_B)  // 110592
#define GEMM_SMEM (2 * STAGE_B)      // 221184

__global__ __launch_bounds__(512, 1)
void gemm_mma(const __nv_bfloat16* __restrict__ Ahi, const __nv_bfloat16* __restrict__ Alo,
              const __nv_bfloat16* __restrict__ Bhi, const __nv_bfloat16* __restrict__ Blo,
              float* __restrict__ outf,
              __nv_bfloat16* __restrict__ outh, __nv_bfloat16* __restrict__ outl,
              const float* __restrict__ rope, int mode)
{
    extern __shared__ char smem[];
    const uint32_t smem_base = smem_u32(smem);
    const int tid = threadIdx.x;
    const int wid = tid >> 5;
    const int lane = tid & 31;
    const int m0 = blockIdx.y * 256;
    const int wM = wid >> 2;         // 0..3
    const int wN = wid & 3;          // 0..3

    const __nv_bfloat16 *bh_p, *bl_p;
    __nv_bfloat16 *oh_p = nullptr, *ol_p = nullptr;
    bool do_rope = false;
    int n0, hsel;
    if (mode == 3) {
        int which = blockIdx.x >> 4;
        int nb = blockIdx.x & 15;
        n0 = nb * 128; hsel = nb;
        if (which == 0)      { bh_p = g_wqT_hi; bl_p = g_wqT_lo; oh_p = g_qh; ol_p = g_ql; do_rope = true; }
        else if (which == 1) { bh_p = g_wkT_hi; bl_p = g_wkT_lo; oh_p = g_kh; ol_p = g_kl; do_rope = true; }
        else                 { bh_p = g_wvT_hi; bl_p = g_wvT_lo; oh_p = g_vh; ol_p = g_vl; }
    } else {
        n0 = blockIdx.x * 128; hsel = blockIdx.x;
        bh_p = Bhi; bl_p = Blo; oh_p = outh; ol_p = outl;
    }

    const char* srcAh = (const char*)(Ahi + (size_t)m0 * E_DIM);
    const char* srcAl = (const char*)(Alo + (size_t)m0 * E_DIM);
    const char* srcBh = (const char*)(bh_p + (size_t)n0 * E_DIM);
    const char* srcBl = (const char*)(bl_p + (size_t)n0 * E_DIM);

    auto issue_chunk = [&](int c, int p) {
        uint32_t sb = smem_base + p * STAGE_B;
        const int kb = c * 128;   // byte offset of k-chunk in a 4096B row
        // A hi/lo: 256 rows x 8 chunks = 2048 each
#pragma unroll
        for (int i = 0; i < 4; i++) {
            int idx = tid + i * 512;
            int row = idx >> 3, c16 = idx & 7;
            uint32_t d = row * ROW_B + c16 * 16;
            CP_ASYNC16(sb + d,            srcAh + (size_t)row * 4096 + kb + c16 * 16);
            CP_ASYNC16(sb + A_TILE_B + d, srcAl + (size_t)row * 4096 + kb + c16 * 16);
        }
        // B hi/lo: 128 rows x 8 chunks = 1024 each
#pragma unroll
        for (int i = 0; i < 2; i++) {
            int idx = tid + i * 512;
            int row = idx >> 3, c16 = idx & 7;
            uint32_t d = row * ROW_B + c16 * 16;
            CP_ASYNC16(sb + 2 * A_TILE_B + d,            srcBh + (size_t)row * 4096 + kb + c16 * 16);
            CP_ASYNC16(sb + 2 * A_TILE_B + B_TILE_B + d, srcBl + (size_t)row * 4096 + kb + c16 * 16);
        }
    };

    float acc[4][4][4];
#pragma unroll
    for (int mt = 0; mt < 4; mt++)
#pragma unroll
        for (int nt = 0; nt < 4; nt++)
#pragma unroll
            for (int e = 0; e < 4; e++) acc[mt][nt][e] = 0.0f;

    const int a_row = (lane & 15);
    const int a_kb = (lane >> 4) * 16;
    const int b_nrow = (lane & 7) | ((lane & 16) >> 1);
    const int b_kb = (lane & 8) ? 16 : 0;

    issue_chunk(0, 0);
    CP_COMMIT();

    for (int c = 0; c < 32; c++) {
        if (c + 1 < 32) {
            issue_chunk(c + 1, (c + 1) & 1);
            CP_COMMIT();
            CP_WAIT1();
        } else {
            CP_WAIT0();
        }
        __syncthreads();

        uint32_t sb = smem_base + (c & 1) * STAGE_B;
        uint32_t aH = sb + (wM * 64 + a_row) * ROW_B + a_kb;
        uint32_t aL = aH + A_TILE_B;
        uint32_t bH = sb + 2 * A_TILE_B + (wN * 32 + b_nrow) * ROW_B + b_kb;
        uint32_t bL = bH + B_TILE_B;

#pragma unroll
        for (int ks = 0; ks < 4; ks++) {
            uint32_t ah[4][4], al[4][4], bh[4][2], bl[4][2];
#pragma unroll
            for (int mt = 0; mt < 4; mt++) {
                LDSM4(ah[mt][0], ah[mt][1], ah[mt][2], ah[mt][3],
                      aH + mt * (16 * ROW_B) + ks * 32);
                LDSM4(al[mt][0], al[mt][1], al[mt][2], al[mt][3],
                      aL + mt * (16 * ROW_B) + ks * 32);
            }
#pragma unroll
            for (int bt = 0; bt < 2; bt++) {
                LDSM4(bh[bt * 2][0], bh[bt * 2][1], bh[bt * 2 + 1][0], bh[bt * 2 + 1][1],
                      bH + bt * (16 * ROW_B) + ks * 32);
                LDSM4(bl[bt * 2][0], bl[bt * 2][1], bl[bt * 2 + 1][0], bl[bt * 2 + 1][1],
                      bL + bt * (16 * ROW_B) + ks * 32);
            }
#pragma unroll
            for (int mt = 0; mt < 4; mt++)
#pragma unroll
                for (int nt = 0; nt < 4; nt++) {
                    MMA16816(acc[mt][nt], ah[mt], bh[nt]);
                    MMA16816(acc[mt][nt], ah[mt], bl[nt]);
                    MMA16816(acc[mt][nt], al[mt], bh[nt]);
                }
        }
        __syncthreads();
    }

    // epilogue through smem so RoPE pairs d/d+64 are thread-local
    float* csm = (float*)smem;     // [256][132]
    const int g = lane >> 2;
    const int tg = lane & 3;
#pragma unroll
    for (int mt = 0; mt < 4; mt++)
#pragma unroll
        for (int nt = 0; nt < 4; nt++) {
            int r = wM * 64 + mt * 16 + g;
            int col = wN * 32 + nt * 8 + tg * 2;
            csm[r * 132 + col]           = acc[mt][nt][0];
            csm[r * 132 + col + 1]       = acc[mt][nt][1];
            csm[(r + 8) * 132 + col]     = acc[mt][nt][2];
            csm[(r + 8) * 132 + col + 1] = acc[mt][nt][3];
        }
    __syncthreads();

#pragma unroll 4
    for (int it = 0; it < 32; it++) {
        int idx = tid + it * 512;          // 0..16383
        int row = idx >> 6;                // 0..255
        int d = idx & 63;
        float lo = csm[row * 132 + d];
        float hi = csm[row * 132 + d + 64];
        int s = m0 + row;
        if (mode == 0) {
            float* orow = outf + (size_t)s * E_DIM + n0;
            orow[d] = lo;
            orow[d + 64] = hi;
        } else {
            if (do_rope) {
                float ang = rope[s * (D_HEAD / 2) + d];
                float sn, cs;
                __sincosf(ang, &sn, &cs);
                float nlo = lo * cs - hi * sn;
                float nhi = hi * cs + lo * sn;
                lo = nlo; hi = nhi;
            }
            size_t base = ((size_t)hsel * S_DIM + s) * D_HEAD;
            __nv_bfloat16 hl = __float2bfloat16(lo);
            __nv_bfloat16 hh = __float2bfloat16(hi);
            oh_p[base + d]      = hl;
            oh_p[base + d + 64] = hh;
            ol_p[base + d]      = __float2bfloat16(lo - __bfloat162float(hl));
            ol_p[base + d + 64] = __float2bfloat16(hi - __bfloat162float(hh));
        }
    }
}

// ---------------------------------------------------------------------------
// Block-sparse attention on mma.sync bf16 (FA2-style), CTA per (q-tile, head).
// Fully-masked anchor tiles (a > t) are skipped — exact (reference weights 0).
// ---------------------------------------------------------------------------
#define NEG_BIG (-1e10f)
#define ATT_TILE 32768
#define ATT_SMEM (6 * ATT_TILE)   // 196608

__global__ __launch_bounds__(256, 1)
void attn_mma(const int* __restrict__ anchors, int kanch)
{
    extern __shared__ char smn[];
    __shared__ int s_tiles[16];
    __shared__ int s_cnt;
    const uint32_t base = smem_u32(smn);
    const uint32_t Qh = base,            Ql = base + ATT_TILE;
    const uint32_t Kh = base + 2*ATT_TILE, Kl = base + 3*ATT_TILE;
    const uint32_t Vh = base + 4*ATT_TILE, Vl = base + 5*ATT_TILE;

    const int t = blockIdx.x, h = blockIdx.y;
    const int tid = threadIdx.x;
    const int w = tid >> 5, lane = tid & 31;
    const int g = lane >> 2, tq = lane & 3;
    const float scale = 0.088388347648318447f;

    // build filtered tile list: anchors <= t (duplicates kept), then local t
    const int abase = (h * T_NUM + t) * kanch;
    if (tid == 0) {
        int n = 0;
        for (int i = 0; i < kanch; i++) {
            int a = anchors[abase + i];
            if (a <= t) s_tiles[n++] = a;
        }
        s_tiles[n++] = t;
        s_cnt = n;
    }
    __syncthreads();
    const int cnt = s_cnt;
    int tile = s_tiles[0];

    auto load_tile2 = [&](uint32_t dh, uint32_t dl,
                          const __nv_bfloat16* sh, const __nv_bfloat16* sl, int tl) {
        const char* ph = (const char*)(sh + ((size_t)h * S_DIM + (size_t)tl * 128) * D_HEAD);
        const char* pl = (const char*)(sl + ((size_t)h * S_DIM + (size_t)tl * 128) * D_HEAD);
        for (int i = tid; i < 2048; i += 256) {
            int row = i >> 4, c16 = i & 15;
            uint32_t off = row * 256 + ((c16 ^ (row & 7)) << 4);
            CP_ASYNC16(dh + off, ph + (size_t)row * 256 + c16 * 16);
            CP_ASYNC16(dl + off, pl + (size_t)row * 256 + c16 * 16);
        }
    };

    // group0: Q + K0 ; group1: V0
    load_tile2(Qh, Ql, g_qh, g_ql, t);
    load_tile2(Kh, Kl, g_kh, g_kl, tile);
    CP_COMMIT();
    load_tile2(Vh, Vl, g_vh, g_vl, tile);
    CP_COMMIT();

    float o[16][4];
#pragma unroll
    for (int j = 0; j < 16; j++)
#pragma unroll
        for (int e = 0; e < 4; e++) o[j][e] = 0.0f;
    float m0 = -1e30f, m1 = -1e30f, l0 = 0.0f, l1 = 0.0f;

    const int wrow = w * 16;
    const int arow = wrow + (lane & 15);
    const int asw = arow & 7;
    const int ahc = lane >> 4;
    const int bnr = (lane & 7) | ((lane & 16) >> 1);
    const int bhc = (lane & 8) >> 3;
    const int vrl = lane & 15;
    const int vhc = lane >> 4;

    for (int it = 0; it < cnt; it++) {
        const bool have_next = (it + 1 < cnt);
        const int nx = have_next ? s_tiles[it + 1] : 0;

        CP_WAIT1();          // K_it (and Q on it==0) ready
        __syncthreads();

        // ---- S = Q K^T (3 split terms) ----
        float s[16][4];
#pragma unroll
        for (int j = 0; j < 16; j++)
#pragma unroll
            for (int e = 0; e < 4; e++) s[j][e] = 0.0f;

#pragma unroll
        for (int ks = 0; ks < 8; ks++) {
            uint32_t qh4[4], ql4[4];
            uint32_t aoff = arow * 256 + (((ks * 2 + ahc) ^ asw) << 4);
            LDSM4(qh4[0], qh4[1], qh4[2], qh4[3], Qh + aoff);
            LDSM4(ql4[0], ql4[1], ql4[2], ql4[3], Ql + aoff);
#pragma unroll
            for (int nb = 0; nb < 8; nb++) {
                int br = nb * 16 + bnr;
                uint32_t boff = br * 256 + (((ks * 2 + bhc) ^ (br & 7)) << 4);
                uint32_t kh4[4], kl4[4];
                LDSM4(kh4[0], kh4[1], kh4[2], kh4[3], Kh + boff);
                LDSM4(kl4[0], kl4[1], kl4[2], kl4[3], Kl + boff);
                uint32_t b0h[2] = {kh4[0], kh4[1]}, b1h[2] = {kh4[2], kh4[3]};
                uint32_t b0l[2] = {kl4[0], kl4[1]}, b1l[2] = {kl4[2], kl4[3]};
                MMA16816(s[2 * nb],     qh4, b0h);
                MMA16816(s[2 * nb],     qh4, b0l);
                MMA16816(s[2 * nb],     ql4, b0h);
                MMA16816(s[2 * nb + 1], qh4, b1h);
                MMA16816(s[2 * nb + 1], qh4, b1l);
                MMA16816(s[2 * nb + 1], ql4, b1h);
            }
        }
        __syncthreads();                 // all warps done reading K
        if (have_next) load_tile2(Kh, Kl, g_kh, g_kl, nx);
        CP_COMMIT();

        // ---- mask + online softmax (quad shuffles only) ----
        const int qp0 = t * 128 + wrow + g;
        const int qp1 = qp0 + 8;
        const int kb = tile * 128 + 2 * tq;
        float mx0 = -1e30f, mx1 = -1e30f;
#pragma unroll
        for (int j = 0; j < 16; j++) {
            int kc = kb + 8 * j;
            s[j][0] = (kc     > qp0) ? NEG_BIG : s[j][0] * scale;
            s[j][1] = (kc + 1 > qp0) ? NEG_BIG : s[j][1] * scale;
            s[j][2] = (kc     > qp1) ? NEG_BIG : s[j][2] * scale;
            s[j][3] = (kc + 1 > qp1) ? NEG_BIG : s[j][3] * scale;
            mx0 = fmaxf(mx0, fmaxf(s[j][0], s[j][1]));
            mx1 = fmaxf(mx1, fmaxf(s[j][2], s[j][3]));
        }
        mx0 = fmaxf(mx0, __shfl_xor_sync(0xffffffffu, mx0, 1));
        mx0 = fmaxf(mx0, __shfl_xor_sync(0xffffffffu, mx0, 2));
        mx1 = fmaxf(mx1, __shfl_xor_sync(0xffffffffu, mx1, 1));
        mx1 = fmaxf(mx1, __shfl_xor_sync(0xffffffffu, mx1, 2));
        const float mn0 = fmaxf(m0, mx0), mn1 = fmaxf(m1, mx1);
        const float f0 = __expf(m0 - mn0), f1 = __expf(m1 - mn1);
        float ls0 = 0.0f, ls1 = 0.0f;
#pragma unroll
        for (int j = 0; j < 16; j++) {
            s[j][0] = __expf(s[j][0] - mn0);
            s[j][1] = __expf(s[j][1] - mn0);
            s[j][2] = __expf(s[j][2] - mn1);
            s[j][3] = __expf(s[j][3] - mn1);
            ls0 += s[j][0] + s[j][1];
            ls1 += s[j][2] + s[j][3];
        }
        ls0 += __shfl_xor_sync(0xffffffffu, ls0, 1);
        ls0 += __shfl_xor_sync(0xffffffffu, ls0, 2);
        ls1 += __shfl_xor_sync(0xffffffffu, ls1, 1);
        ls1 += __shfl_xor_sync(0xffffffffu, ls1, 2);
        l0 = l0 * f0 + ls0; l1 = l1 * f1 + ls1;
        m0 = mn0; m1 = mn1;
#pragma unroll
        for (int j = 0; j < 16; j++) {
            o[j][0] *= f0; o[j][1] *= f0;
            o[j][2] *= f1; o[j][3] *= f1;
        }

        CP_WAIT1();          // V_it ready
        __syncthreads();

        // ---- O += P V (3 split terms), P packed from S fragments ----
#pragma unroll
        for (int ks = 0; ks < 8; ks++) {
            uint32_t ph[4], pl[4];
            ph[0] = pack_bf16x2(s[2 * ks][0], s[2 * ks][1]);
            ph[1] = pack_bf16x2(s[2 * ks][2], s[2 * ks][3]);
            ph[2] = pack_bf16x2(s[2 * ks + 1][0], s[2 * ks + 1][1]);
            ph[3] = pack_bf16x2(s[2 * ks + 1][2], s[2 * ks + 1][3]);
            pl[0] = pack_bf16x2_res(s[2 * ks][0], s[2 * ks][1], ph[0]);
            pl[1] = pack_bf16x2_res(s[2 * ks][2], s[2 * ks][3], ph[1]);
            pl[2] = pack_bf16x2_res(s[2 * ks + 1][0], s[2 * ks + 1][1], ph[2]);
            pl[3] = pack_bf16x2_res(s[2 * ks + 1][2], s[2 * ks + 1][3], ph[3]);
            int vr = ks * 16 + vrl;
#pragma unroll
            for (int dd = 0; dd < 8; dd++) {
                uint32_t voff = vr * 256 + (((dd * 2 + vhc) ^ (vr & 7)) << 4);
                uint32_t vh4[4], vl4[4];
                LDSM4T(vh4[0], vh4[1], vh4[2], vh4[3], Vh + voff);
                LDSM4T(vl4[0], vl4[1], vl4[2], vl4[3], Vl + voff);
                uint32_t b0h[2] = {vh4[0], vh4[1]}, b1h[2] = {vh4[2], vh4[3]};
                uint32_t b0l[2] = {vl4[0], vl4[1]}, b1l[2] = {vl4[2], vl4[3]};
                MMA16816(o[2 * dd],     ph, b0h);
                MMA16816(o[2 * dd],     pl, b0h);
                MMA16816(o[2 * dd],     ph, b0l);
                MMA16816(o[2 * dd + 1], ph, b1h);
                MMA16816(o[2 * dd + 1], pl, b1h);
                MMA16816(o[2 * dd + 1], ph, b1l);
            }
        }
        __syncthreads();                 // all warps done reading V
        if (have_next) load_tile2(Vh, Vl, g_vh, g_vl, nx);
        CP_COMMIT();

        tile = nx;
    }

    // ---- epilogue: normalize, bf16 hi/lo split to [S, H*D] ----
    const float i0 = 1.0f / l0, i1 = 1.0f / l1;
    const int s0 = t * 128 + wrow + g, s1 = s0 + 8;
#pragma unroll
    for (int j = 0; j < 16; j++) {
        int col = h * D_HEAD + 8 * j + 2 * tq;
        float v0 = o[j][0] * i0, v1 = o[j][1] * i0;
        uint32_t hv = pack_bf16x2(v0, v1);
        uint32_t lv = pack_bf16x2_res(v0, v1, hv);
        *(uint32_t*)(g_att_hi + (size_t)s0 * E_DIM + col) = hv;
        *(uint32_t*)(g_att_lo + (size_t)s0 * E_DIM + col) = lv;
        v0 = o[j][2] * i1; v1 = o[j][3] * i1;
        hv = pack_bf16x2(v0, v1);
        lv = pack_bf16x2_res(v0, v1, hv);
        *(uint32_t*)(g_att_hi + (size_t)s1 * E_DIM + col) = hv;
        *(uint32_t*)(g_att_lo + (size_t)s1 * E_DIM + col) = lv;
    }
}

// ---------------------------------------------------------------------------
extern "C" void kernel_launch(void* const* d_in, const int* in_sizes, int n_in,
                              void* d_out, int out_size)
{
    const float* x    = (const float*)d_in[0];
    const float* wq   = (const float*)d_in[1];
    const float* wk   = (const float*)d_in[2];
    const float* wv   = (const float*)d_in[3];
    const float* wo   = (const float*)d_in[4];
    const float* rope = (const float*)d_in[5];
    const int* anchors = (const int*)d_in[6];
    float* out = (float*)d_out;

    const int kanch = in_sizes[6] / (H_NUM * T_NUM);  // 8

    __nv_bfloat16 *xh, *xl, *oTh, *oTl, *ah, *al;
    cudaGetSymbolAddress((void**)&xh, g_x_hi);
    cudaGetSymbolAddress((void**)&xl, g_x_lo);
    cudaGetSymbolAddress((void**)&oTh, g_woT_hi);
    cudaGetSymbolAddress((void**)&oTl, g_woT_lo);
    cudaGetSymbolAddress((void**)&ah, g_att_hi);
    cudaGetSymbolAddress((void**)&al, g_att_lo);

    cudaFuncSetAttribute(gemm_mma, cudaFuncAttributeMaxDynamicSharedMemorySize, GEMM_SMEM);
    cudaFuncSetAttribute(attn_mma, cudaFuncAttributeMaxDynamicSharedMemorySize, ATT_SMEM);

    // 1. split x -> bf16 hi/lo
    split_kernel<<<(S_DIM * E_DIM / 4 + 255) / 256, 256>>>(x, xh, xl, S_DIM * E_DIM);

    // 2. fused transpose+split of all weights
    dim3 tgrid(E_DIM / 32, E_DIM / 32, 4), tblk(32, 8);
    transpose_split4<<<tgrid, tblk>>>(wq, wk, wv, wo);

    // 3. fused QKV projection (RoPE inside), bf16 hi/lo head-major
    dim3 qkvgrid(48, S_DIM / 256);  // (48, 16)
    gemm_mma<<<qkvgrid, 512, GEMM_SMEM>>>(xh, xl, nullptr, nullptr,
                                          nullptr, nullptr, nullptr, rope, 3);

    // 4. block-sparse attention (skips fully-masked tiles)
    dim3 agrid(T_NUM, H_NUM);
    attn_mma<<<agrid, 256, ATT_SMEM>>>(anchors, kanch);

    // 5. out projection -> d_out   (5th launch: ncu profiles this one)
    dim3 ogrid(E_DIM / 128, S_DIM / 256);  // (16, 16)
    gemm_mma<<<ogrid, 512, GEMM_SMEM>>>(ah, al, oTh, oTl, out, nullptr, nullptr,
                                        nullptr, 0);
}

// round 7
// speedup vs baseline: 4.3126x; 1.3596x over previous
#include <cuda_runtime.h>
#include <cuda_fp16.h>
#include <math.h>
#include <stdint.h>

#define S_DIM 4096
#define E_DIM 2048
#define H_NUM 16
#define D_HEAD 128
#define T_NUM 32

// ---------------------------------------------------------------------------
// Scratch (__device__ globals; allocation-free rule)
// A-side (activations): 2-term fp16 (exact); B-side (weights/K/V): single fp16
// ---------------------------------------------------------------------------
__device__ __half g_x_hi[S_DIM * E_DIM];
__device__ __half g_x_lo[S_DIM * E_DIM];
__device__ __half g_wqT[E_DIM * E_DIM];
__device__ __half g_wkT[E_DIM * E_DIM];
__device__ __half g_wvT[E_DIM * E_DIM];
__device__ __half g_woT[E_DIM * E_DIM];
// head-major fp16 QKV (RoPE already applied to Q,K)
__device__ __half g_qh[H_NUM * S_DIM * D_HEAD];
__device__ __half g_ql[H_NUM * S_DIM * D_HEAD];
__device__ __half g_k16[H_NUM * S_DIM * D_HEAD];
__device__ __half g_v16[H_NUM * S_DIM * D_HEAD];
__device__ __half g_att_hi[S_DIM * E_DIM];
__device__ __half g_att_lo[S_DIM * E_DIM];

// ---------------------------------------------------------------------------
// base-ISA PTX helpers (compute_103 virtual arch: no tcgen05/TMA)
// ---------------------------------------------------------------------------
__device__ __forceinline__ uint32_t smem_u32(const void* p) {
    uint32_t a;
    asm("{ .reg .u64 t; cvta.to.shared.u64 t, %1; cvt.u32.u64 %0, t; }" : "=r"(a) : "l"(p));
    return a;
}

#define CP_ASYNC16(dst, src) \
    asm volatile("cp.async.cg.shared.global [%0], [%1], 16;" :: "r"(dst), "l"(src))
#define CP_COMMIT() asm volatile("cp.async.commit_group;" ::: "memory")
#define CP_WAIT1() asm volatile("cp.async.wait_group 1;" ::: "memory")
#define CP_WAIT0() asm volatile("cp.async.wait_group 0;" ::: "memory")

#define LDSM4(r0, r1, r2, r3, addr) \
    asm volatile("ldmatrix.sync.aligned.m8n8.x4.shared.b16 {%0,%1,%2,%3}, [%4];" \
        : "=r"(r0), "=r"(r1), "=r"(r2), "=r"(r3) : "r"(addr))
#define LDSM4T(r0, r1, r2, r3, addr) \
    asm volatile("ldmatrix.sync.aligned.m8n8.x4.trans.shared.b16 {%0,%1,%2,%3}, [%4];" \
        : "=r"(r0), "=r"(r1), "=r"(r2), "=r"(r3) : "r"(addr))

#define MMA16816(d, a, b) \
    asm volatile("mma.sync.aligned.m16n8k16.row.col.f32.f16.f16.f32 " \
        "{%0,%1,%2,%3}, {%4,%5,%6,%7}, {%8,%9}, {%0,%1,%2,%3};" \
        : "+f"((d)[0]), "+f"((d)[1]), "+f"((d)[2]), "+f"((d)[3]) \
        : "r"((a)[0]), "r"((a)[1]), "r"((a)[2]), "r"((a)[3]), \
          "r"((b)[0]), "r"((b)[1]))

__device__ __forceinline__ uint32_t pack_h2(float a, float b) {
    __half2 v = __floats2half2_rn(a, b);
    return *(uint32_t*)&v;
}
__device__ __forceinline__ uint32_t pack_h2_res(float a, float b, uint32_t hibits) {
    __half2 h = *(__half2*)&hibits;
    return pack_h2(a - __half2float(h.x), b - __half2float(h.y));
}

// ---------------------------------------------------------------------------
// fp32 -> fp16 hi/lo split (element-wise) for x
// ---------------------------------------------------------------------------
__global__ void split_kernel(const float* __restrict__ in,
                             __half* __restrict__ hi,
                             __half* __restrict__ lo, int n)
{
    int i = (blockIdx.x * blockDim.x + threadIdx.x) * 4;
    if (i >= n) return;
    float4 v = *(const float4*)(in + i);
    __half2 hA = __floats2half2_rn(v.x, v.y);
    __half2 hB = __floats2half2_rn(v.z, v.w);
    __half2 lA = __floats2half2_rn(v.x - __half2float(hA.x), v.y - __half2float(hA.y));
    __half2 lB = __floats2half2_rn(v.z - __half2float(hB.x), v.w - __half2float(hB.y));
    *(__half2*)(hi + i) = hA;
    *(__half2*)(hi + i + 2) = hB;
    *(__half2*)(lo + i) = lA;
    *(__half2*)(lo + i + 2) = lB;
}

// ---------------------------------------------------------------------------
// fused transpose of all 4 weight matrices: w[K,N] -> wT[N,K] single fp16
// ---------------------------------------------------------------------------
__global__ void transpose4(const float* __restrict__ wq, const float* __restrict__ wk,
                           const float* __restrict__ wv, const float* __restrict__ wo)
{
    __shared__ float tile[32][33];
    const float* w;
    __half* oT;
    switch (blockIdx.z) {
        case 0:  w = wq; oT = g_wqT; break;
        case 1:  w = wk; oT = g_wkT; break;
        case 2:  w = wv; oT = g_wvT; break;
        default: w = wo; oT = g_woT; break;
    }
    int n = blockIdx.x * 32 + threadIdx.x;
    int k0 = blockIdx.y * 32;
#pragma unroll
    for (int j = 0; j < 32; j += 8)
        tile[threadIdx.y + j][threadIdx.x] = w[(k0 + threadIdx.y + j) * E_DIM + n];
    __syncthreads();
#pragma unroll
    for (int j = 0; j < 32; j += 8) {
        int orow = blockIdx.x * 32 + threadIdx.y + j;
        int ocol = k0 + threadIdx.x;
        oT[orow * E_DIM + ocol] = __float2half(tile[threadIdx.x][threadIdx.y + j]);
    }
}

// ---------------------------------------------------------------------------
// HMMA fp16 GEMM — A 2-term (Ah+Al), B single. CTA 256x128, 512 threads
// (16 warps 4Mx4N), K-chunk 64, cp.async double buffer. 2 MMA terms.
// mode 0: fp32 row-major out[M,2048]
// mode 3: fused QKV — blockIdx.x = which*16 + nb:
//         which 0: Q (RoPE, 2-term out), 1: K (RoPE, single), 2: V (single)
// ---------------------------------------------------------------------------
#define ROW_B 144
#define A_TILE_B (256 * ROW_B)       // 36864
#define B_TILE_B (128 * ROW_B)       // 18432
#define STAGE_B (2 * A_TILE_B + B_TILE_B)  // 92160
#define GEMM_SMEM (2 * STAGE_B)      // 184320

__global__ __launch_bounds__(512, 1)
void gemm_mma(const __half* __restrict__ Ahi, const __half* __restrict__ Alo,
              const __half* __restrict__ Bs,
              float* __restrict__ outf, const float* __restrict__ rope, int mode)
{
    extern __shared__ char smem[];
    const uint32_t smem_base = smem_u32(smem);
    const int tid = threadIdx.x;
    const int wid = tid >> 5;
    const int lane = tid & 31;
    const int m0 = blockIdx.y * 256;
    const int wM = wid >> 2;         // 0..3
    const int wN = wid & 3;          // 0..3

    const __half* b_p;
    int n0, hsel, which = -1;
    if (mode == 3) {
        which = blockIdx.x >> 4;
        int nb = blockIdx.x & 15;
        n0 = nb * 128; hsel = nb;
        b_p = (which == 0) ? g_wqT : (which == 1) ? g_wkT : g_wvT;
    } else {
        n0 = blockIdx.x * 128; hsel = blockIdx.x;
        b_p = Bs;
    }

    const char* srcAh = (const char*)(Ahi + (size_t)m0 * E_DIM);
    const char* srcAl = (const char*)(Alo + (size_t)m0 * E_DIM);
    const char* srcB  = (const char*)(b_p + (size_t)n0 * E_DIM);

    auto issue_chunk = [&](int c, int p) {
        uint32_t sb = smem_base + p * STAGE_B;
        const int kb = c * 128;   // byte offset of k-chunk in a 4096B row
#pragma unroll
        for (int i = 0; i < 4; i++) {
            int idx = tid + i * 512;
            int row = idx >> 3, c16 = idx & 7;
            uint32_t d = row * ROW_B + c16 * 16;
            CP_ASYNC16(sb + d,            srcAh + (size_t)row * 4096 + kb + c16 * 16);
            CP_ASYNC16(sb + A_TILE_B + d, srcAl + (size_t)row * 4096 + kb + c16 * 16);
        }
#pragma unroll
        for (int i = 0; i < 2; i++) {
            int idx = tid + i * 512;
            int row = idx >> 3, c16 = idx & 7;
            uint32_t d = row * ROW_B + c16 * 16;
            CP_ASYNC16(sb + 2 * A_TILE_B + d, srcB + (size_t)row * 4096 + kb + c16 * 16);
        }
    };

    float acc[4][4][4];
#pragma unroll
    for (int mt = 0; mt < 4; mt++)
#pragma unroll
        for (int nt = 0; nt < 4; nt++)
#pragma unroll
            for (int e = 0; e < 4; e++) acc[mt][nt][e] = 0.0f;

    const int a_row = (lane & 15);
    const int a_kb = (lane >> 4) * 16;
    const int b_nrow = (lane & 7) | ((lane & 16) >> 1);
    const int b_kb = (lane & 8) ? 16 : 0;

    issue_chunk(0, 0);
    CP_COMMIT();

    for (int c = 0; c < 32; c++) {
        if (c + 1 < 32) {
            issue_chunk(c + 1, (c + 1) & 1);
            CP_COMMIT();
            CP_WAIT1();
        } else {
            CP_WAIT0();
        }
        __syncthreads();

        uint32_t sb = smem_base + (c & 1) * STAGE_B;
        uint32_t aH = sb + (wM * 64 + a_row) * ROW_B + a_kb;
        uint32_t aL = aH + A_TILE_B;
        uint32_t bB = sb + 2 * A_TILE_B + (wN * 32 + b_nrow) * ROW_B + b_kb;

#pragma unroll
        for (int ks = 0; ks < 4; ks++) {
            uint32_t ah[4][4], al[4][4], b[4][2];
#pragma unroll
            for (int mt = 0; mt < 4; mt++) {
                LDSM4(ah[mt][0], ah[mt][1], ah[mt][2], ah[mt][3],
                      aH + mt * (16 * ROW_B) + ks * 32);
                LDSM4(al[mt][0], al[mt][1], al[mt][2], al[mt][3],
                      aL + mt * (16 * ROW_B) + ks * 32);
            }
#pragma unroll
            for (int bt = 0; bt < 2; bt++) {
                LDSM4(b[bt * 2][0], b[bt * 2][1], b[bt * 2 + 1][0], b[bt * 2 + 1][1],
                      bB + bt * (16 * ROW_B) + ks * 32);
            }
#pragma unroll
            for (int mt = 0; mt < 4; mt++)
#pragma unroll
                for (int nt = 0; nt < 4; nt++) {
                    MMA16816(acc[mt][nt], ah[mt], b[nt]);
                    MMA16816(acc[mt][nt], al[mt], b[nt]);
                }
        }
        __syncthreads();
    }

    // epilogue through smem so RoPE pairs d/d+64 are thread-local
    float* csm = (float*)smem;     // [256][132]
    const int g = lane >> 2;
    const int tg = lane & 3;
#pragma unroll
    for (int mt = 0; mt < 4; mt++)
#pragma unroll
        for (int nt = 0; nt < 4; nt++) {
            int r = wM * 64 + mt * 16 + g;
            int col = wN * 32 + nt * 8 + tg * 2;
            csm[r * 132 + col]           = acc[mt][nt][0];
            csm[r * 132 + col + 1]       = acc[mt][nt][1];
            csm[(r + 8) * 132 + col]     = acc[mt][nt][2];
            csm[(r + 8) * 132 + col + 1] = acc[mt][nt][3];
        }
    __syncthreads();

#pragma unroll 4
    for (int it = 0; it < 32; it++) {
        int idx = tid + it * 512;          // 0..16383
        int row = idx >> 6;                // 0..255
        int d = idx & 63;
        float lo = csm[row * 132 + d];
        float hi = csm[row * 132 + d + 64];
        int s = m0 + row;
        if (mode == 0) {
            float* orow = outf + (size_t)s * E_DIM + n0;
            orow[d] = lo;
            orow[d + 64] = hi;
        } else {
            if (which <= 1) {              // RoPE for Q and K
                float ang = rope[s * (D_HEAD / 2) + d];
                float sn, cs;
                __sincosf(ang, &sn, &cs);
                float nlo = lo * cs - hi * sn;
                float nhi = hi * cs + lo * sn;
                lo = nlo; hi = nhi;
            }
            size_t base = ((size_t)hsel * S_DIM + s) * D_HEAD;
            if (which == 0) {              // Q: 2-term (A-side, exact)
                __half hl = __float2half(lo);
                __half hh = __float2half(hi);
                g_qh[base + d]      = hl;
                g_qh[base + d + 64] = hh;
                g_ql[base + d]      = __float2half(lo - __half2float(hl));
                g_ql[base + d + 64] = __float2half(hi - __half2float(hh));
            } else if (which == 1) {       // K: single fp16
                g_k16[base + d]      = __float2half(lo);
                g_k16[base + d + 64] = __float2half(hi);
            } else {                       // V: single fp16
                g_v16[base + d]      = __float2half(lo);
                g_v16[base + d + 64] = __float2half(hi);
            }
        }
    }
}

// ---------------------------------------------------------------------------
// Block-sparse attention, fp16 mma.sync: Q 2-term (A-side), K/V single (B-side).
// CTA per (q-tile, head); fully-masked anchor tiles skipped (exact).
// smem: Qh, Ql, K, V  (4 x 32KB, 256B swizzled rows)
// ---------------------------------------------------------------------------
#define NEG_BIG (-1e10f)
#define ATT_TILE 32768
#define ATT_SMEM (4 * ATT_TILE)   // 131072

__global__ __launch_bounds__(256, 1)
void attn_mma(const int* __restrict__ anchors, int kanch)
{
    extern __shared__ char smn[];
    __shared__ int s_tiles[16];
    __shared__ int s_cnt;
    const uint32_t base = smem_u32(smn);
    const uint32_t Qh = base,              Ql = base + ATT_TILE;
    const uint32_t Kb = base + 2*ATT_TILE, Vb = base + 3*ATT_TILE;

    const int t = blockIdx.x, h = blockIdx.y;
    const int tid = threadIdx.x;
    const int w = tid >> 5, lane = tid & 31;
    const int g = lane >> 2, tq = lane & 3;
    const float scale = 0.088388347648318447f;

    // build filtered tile list: anchors <= t (duplicates kept), then local t
    const int abase = (h * T_NUM + t) * kanch;
    if (tid == 0) {
        int n = 0;
        for (int i = 0; i < kanch; i++) {
            int a = anchors[abase + i];
            if (a <= t) s_tiles[n++] = a;
        }
        s_tiles[n++] = t;
        s_cnt = n;
    }
    __syncthreads();
    const int cnt = s_cnt;
    int tile = s_tiles[0];

    auto load_tile = [&](uint32_t dst, const __half* src, int tl) {
        const char* p = (const char*)(src + ((size_t)h * S_DIM + (size_t)tl * 128) * D_HEAD);
        for (int i = tid; i < 2048; i += 256) {
            int row = i >> 4, c16 = i & 15;
            uint32_t off = row * 256 + ((c16 ^ (row & 7)) << 4);
            CP_ASYNC16(dst + off, p + (size_t)row * 256 + c16 * 16);
        }
    };

    // group0: Q(h,l) + K0 ; group1: V0
    load_tile(Qh, g_qh, t);
    load_tile(Ql, g_ql, t);
    load_tile(Kb, g_k16, tile);
    CP_COMMIT();
    load_tile(Vb, g_v16, tile);
    CP_COMMIT();

    float o[16][4];
#pragma unroll
    for (int j = 0; j < 16; j++)
#pragma unroll
        for (int e = 0; e < 4; e++) o[j][e] = 0.0f;
    float m0 = -1e30f, m1 = -1e30f, l0 = 0.0f, l1 = 0.0f;

    const int wrow = w * 16;
    const int arow = wrow + (lane & 15);
    const int asw = arow & 7;
    const int ahc = lane >> 4;
    const int bnr = (lane & 7) | ((lane & 16) >> 1);
    const int bhc = (lane & 8) >> 3;
    const int vrl = lane & 15;
    const int vhc = lane >> 4;

    for (int it = 0; it < cnt; it++) {
        const bool have_next = (it + 1 < cnt);
        const int nx = have_next ? s_tiles[it + 1] : 0;

        CP_WAIT1();          // K_it (and Q on it==0) ready
        __syncthreads();

        // ---- S = Q K^T (Qh + Ql terms) ----
        float s[16][4];
#pragma unroll
        for (int j = 0; j < 16; j++)
#pragma unroll
            for (int e = 0; e < 4; e++) s[j][e] = 0.0f;

#pragma unroll
        for (int ks = 0; ks < 8; ks++) {
            uint32_t qh4[4], ql4[4];
            uint32_t aoff = arow * 256 + (((ks * 2 + ahc) ^ asw) << 4);
            LDSM4(qh4[0], qh4[1], qh4[2], qh4[3], Qh + aoff);
            LDSM4(ql4[0], ql4[1], ql4[2], ql4[3], Ql + aoff);
#pragma unroll
            for (int nb = 0; nb < 8; nb++) {
                int br = nb * 16 + bnr;
                uint32_t boff = br * 256 + (((ks * 2 + bhc) ^ (br & 7)) << 4);
                uint32_t k4[4];
                LDSM4(k4[0], k4[1], k4[2], k4[3], Kb + boff);
                uint32_t b0[2] = {k4[0], k4[1]}, b1[2] = {k4[2], k4[3]};
                MMA16816(s[2 * nb],     qh4, b0);
                MMA16816(s[2 * nb],     ql4, b0);
                MMA16816(s[2 * nb + 1], qh4, b1);
                MMA16816(s[2 * nb + 1], ql4, b1);
            }
        }
        __syncthreads();                 // all warps done reading K
        if (have_next) load_tile(Kb, g_k16, nx);
        CP_COMMIT();

        // ---- mask + online softmax (quad shuffles only) ----
        const int qp0 = t * 128 + wrow + g;
        const int qp1 = qp0 + 8;
        const int kb = tile * 128 + 2 * tq;
        float mx0 = -1e30f, mx1 = -1e30f;
#pragma unroll
        for (int j = 0; j < 16; j++) {
            int kc = kb + 8 * j;
            s[j][0] = (kc     > qp0) ? NEG_BIG : s[j][0] * scale;
            s[j][1] = (kc + 1 > qp0) ? NEG_BIG : s[j][1] * scale;
            s[j][2] = (kc     > qp1) ? NEG_BIG : s[j][2] * scale;
            s[j][3] = (kc + 1 > qp1) ? NEG_BIG : s[j][3] * scale;
            mx0 = fmaxf(mx0, fmaxf(s[j][0], s[j][1]));
            mx1 = fmaxf(mx1, fmaxf(s[j][2], s[j][3]));
        }
        mx0 = fmaxf(mx0, __shfl_xor_sync(0xffffffffu, mx0, 1));
        mx0 = fmaxf(mx0, __shfl_xor_sync(0xffffffffu, mx0, 2));
        mx1 = fmaxf(mx1, __shfl_xor_sync(0xffffffffu, mx1, 1));
        mx1 = fmaxf(mx1, __shfl_xor_sync(0xffffffffu, mx1, 2));
        const float mn0 = fmaxf(m0, mx0), mn1 = fmaxf(m1, mx1);
        const float f0 = __expf(m0 - mn0), f1 = __expf(m1 - mn1);
        float ls0 = 0.0f, ls1 = 0.0f;
#pragma unroll
        for (int j = 0; j < 16; j++) {
            s[j][0] = __expf(s[j][0] - mn0);
            s[j][1] = __expf(s[j][1] - mn0);
            s[j][2] = __expf(s[j][2] - mn1);
            s[j][3] = __expf(s[j][3] - mn1);
            ls0 += s[j][0] + s[j][1];
            ls1 += s[j][2] + s[j][3];
        }
        ls0 += __shfl_xor_sync(0xffffffffu, ls0, 1);
        ls0 += __shfl_xor_sync(0xffffffffu, ls0, 2);
        ls1 += __shfl_xor_sync(0xffffffffu, ls1, 1);
        ls1 += __shfl_xor_sync(0xffffffffu, ls1, 2);
        l0 = l0 * f0 + ls0; l1 = l1 * f1 + ls1;
        m0 = mn0; m1 = mn1;
#pragma unroll
        for (int j = 0; j < 16; j++) {
            o[j][0] *= f0; o[j][1] *= f0;
            o[j][2] *= f1; o[j][3] *= f1;
        }

        CP_WAIT1();          // V_it ready
        __syncthreads();

        // ---- O += P V (Ph + Pl terms), P packed from S fragments ----
#pragma unroll
        for (int ks = 0; ks < 8; ks++) {
            uint32_t ph[4], pl[4];
            ph[0] = pack_h2(s[2 * ks][0], s[2 * ks][1]);
            ph[1] = pack_h2(s[2 * ks][2], s[2 * ks][3]);
            ph[2] = pack_h2(s[2 * ks + 1][0], s[2 * ks + 1][1]);
            ph[3] = pack_h2(s[2 * ks + 1][2], s[2 * ks + 1][3]);
            pl[0] = pack_h2_res(s[2 * ks][0], s[2 * ks][1], ph[0]);
            pl[1] = pack_h2_res(s[2 * ks][2], s[2 * ks][3], ph[1]);
            pl[2] = pack_h2_res(s[2 * ks + 1][0], s[2 * ks + 1][1], ph[2]);
            pl[3] = pack_h2_res(s[2 * ks + 1][2], s[2 * ks + 1][3], ph[3]);
            int vr = ks * 16 + vrl;
#pragma unroll
            for (int dd = 0; dd < 8; dd++) {
                uint32_t voff = vr * 256 + (((dd * 2 + vhc) ^ (vr & 7)) << 4);
                uint32_t v4[4];
                LDSM4T(v4[0], v4[1], v4[2], v4[3], Vb + voff);
                uint32_t b0[2] = {v4[0], v4[1]}, b1[2] = {v4[2], v4[3]};
                MMA16816(o[2 * dd],     ph, b0);
                MMA16816(o[2 * dd],     pl, b0);
                MMA16816(o[2 * dd + 1], ph, b1);
                MMA16816(o[2 * dd + 1], pl, b1);
            }
        }
        __syncthreads();                 // all warps done reading V
        if (have_next) load_tile(Vb, g_v16, nx);
        CP_COMMIT();

        tile = nx;
    }

    // ---- epilogue: normalize, fp16 hi/lo split to [S, H*D] ----
    const float i0 = 1.0f / l0, i1 = 1.0f / l1;
    const int s0 = t * 128 + wrow + g, s1 = s0 + 8;
#pragma unroll
    for (int j = 0; j < 16; j++) {
        int col = h * D_HEAD + 8 * j + 2 * tq;
        float v0 = o[j][0] * i0, v1 = o[j][1] * i0;
        uint32_t hv = pack_h2(v0, v1);
        uint32_t lv = pack_h2_res(v0, v1, hv);
        *(uint32_t*)(g_att_hi + (size_t)s0 * E_DIM + col) = hv;
        *(uint32_t*)(g_att_lo + (size_t)s0 * E_DIM + col) = lv;
        v0 = o[j][2] * i1; v1 = o[j][3] * i1;
        hv = pack_h2(v0, v1);
        lv = pack_h2_res(v0, v1, hv);
        *(uint32_t*)(g_att_hi + (size_t)s1 * E_DIM + col) = hv;
        *(uint32_t*)(g_att_lo + (size_t)s1 * E_DIM + col) = lv;
    }
}

// ---------------------------------------------------------------------------
extern "C" void kernel_launch(void* const* d_in, const int* in_sizes, int n_in,
                              void* d_out, int out_size)
{
    const float* x    = (const float*)d_in[0];
    const float* wq   = (const float*)d_in[1];
    const float* wk   = (const float*)d_in[2];
    const float* wv   = (const float*)d_in[3];
    const float* wo   = (const float*)d_in[4];
    const float* rope = (const float*)d_in[5];
    const int* anchors = (const int*)d_in[6];
    float* out = (float*)d_out;

    const int kanch = in_sizes[6] / (H_NUM * T_NUM);  // 8

    __half *xh, *xl, *woT, *ah, *al;
    cudaGetSymbolAddress((void**)&xh, g_x_hi);
    cudaGetSymbolAddress((void**)&xl, g_x_lo);
    cudaGetSymbolAddress((void**)&woT, g_woT);
    cudaGetSymbolAddress((void**)&ah, g_att_hi);
    cudaGetSymbolAddress((void**)&al, g_att_lo);

    cudaFuncSetAttribute(gemm_mma, cudaFuncAttributeMaxDynamicSharedMemorySize, GEMM_SMEM);
    cudaFuncSetAttribute(attn_mma, cudaFuncAttributeMaxDynamicSharedMemorySize, ATT_SMEM);

    // 1. split x -> fp16 hi/lo
    split_kernel<<<(S_DIM * E_DIM / 4 + 255) / 256, 256>>>(x, xh, xl, S_DIM * E_DIM);

    // 2. fused transpose of all weights (single fp16)
    dim3 tgrid(E_DIM / 32, E_DIM / 32, 4), tblk(32, 8);
    transpose4<<<tgrid, tblk>>>(wq, wk, wv, wo);

    // 3. fused QKV projection (RoPE inside), head-major fp16
    dim3 qkvgrid(48, S_DIM / 256);  // (48, 16)
    gemm_mma<<<qkvgrid, 512, GEMM_SMEM>>>(xh, xl, nullptr, nullptr, rope, 3);

    // 4. block-sparse attention (skips fully-masked tiles)
    dim3 agrid(T_NUM, H_NUM);
    attn_mma<<<agrid, 256, ATT_SMEM>>>(anchors, kanch);

    // 5. out projection -> d_out   (5th launch: ncu profiles this one)
    dim3 ogrid(E_DIM / 128, S_DIM / 256);  // (16, 16)
    gemm_mma<<<ogrid, 512, GEMM_SMEM>>>(ah, al, woT, out, nullptr, 0);
}

// round 9
// speedup vs baseline: 6.7006x; 1.5537x over previous
#include <cuda_runtime.h>
#include <cuda_fp16.h>
#include <math.h>
#include <stdint.h>

#define S_DIM 4096
#define E_DIM 2048
#define H_NUM 16
#define D_HEAD 128
#define T_NUM 32

// ---------------------------------------------------------------------------
// Scratch (__device__ globals; allocation-free rule)
// Single fp16 everywhere except: Q and P (2-term, protect softmax logits)
// ---------------------------------------------------------------------------
__device__ __half g_x16[S_DIM * E_DIM];
__device__ __half g_wqT[E_DIM * E_DIM];
__device__ __half g_wkT[E_DIM * E_DIM];
__device__ __half g_wvT[E_DIM * E_DIM];
__device__ __half g_woT[E_DIM * E_DIM];
// head-major fp16 QKV (RoPE already applied to Q,K); Q kept 2-term
__device__ __half g_qh[H_NUM * S_DIM * D_HEAD];
__device__ __half g_ql[H_NUM * S_DIM * D_HEAD];
__device__ __half g_k16[H_NUM * S_DIM * D_HEAD];
__device__ __half g_v16[H_NUM * S_DIM * D_HEAD];
__device__ __half g_att[S_DIM * E_DIM];

// ---------------------------------------------------------------------------
// base-ISA PTX helpers (compute_103 virtual arch: no tcgen05/TMA)
// ---------------------------------------------------------------------------
__device__ __forceinline__ uint32_t smem_u32(const void* p) {
    uint32_t a;
    asm("{ .reg .u64 t; cvta.to.shared.u64 t, %1; cvt.u32.u64 %0, t; }" : "=r"(a) : "l"(p));
    return a;
}

#define CP_ASYNC16(dst, src) \
    asm volatile("cp.async.cg.shared.global [%0], [%1], 16;" :: "r"(dst), "l"(src))
#define CP_COMMIT() asm volatile("cp.async.commit_group;" ::: "memory")
#define CP_WAIT1() asm volatile("cp.async.wait_group 1;" ::: "memory")
#define CP_WAIT0() asm volatile("cp.async.wait_group 0;" ::: "memory")

#define LDSM4(r0, r1, r2, r3, addr) \
    asm volatile("ldmatrix.sync.aligned.m8n8.x4.shared.b16 {%0,%1,%2,%3}, [%4];" \
        : "=r"(r0), "=r"(r1), "=r"(r2), "=r"(r3) : "r"(addr))
#define LDSM4T(r0, r1, r2, r3, addr) \
    asm volatile("ldmatrix.sync.aligned.m8n8.x4.trans.shared.b16 {%0,%1,%2,%3}, [%4];" \
        : "=r"(r0), "=r"(r1), "=r"(r2), "=r"(r3) : "r"(addr))

#define MMA16816(d, a, b) \
    asm volatile("mma.sync.aligned.m16n8k16.row.col.f32.f16.f16.f32 " \
        "{%0,%1,%2,%3}, {%4,%5,%6,%7}, {%8,%9}, {%0,%1,%2,%3};" \
        : "+f"((d)[0]), "+f"((d)[1]), "+f"((d)[2]), "+f"((d)[3]) \
        : "r"((a)[0]), "r"((a)[1]), "r"((a)[2]), "r"((a)[3]), \
          "r"((b)[0]), "r"((b)[1]))

__device__ __forceinline__ uint32_t pack_h2(float a, float b) {
    __half2 v = __floats2half2_rn(a, b);
    return *(uint32_t*)&v;
}
__device__ __forceinline__ uint32_t pack_h2_res(float a, float b, uint32_t hibits) {
    __half2 h = *(__half2*)&hibits;
    return pack_h2(a - __half2float(h.x), b - __half2float(h.y));
}

// ---------------------------------------------------------------------------
// fp32 -> fp16 convert (x)
// ---------------------------------------------------------------------------
__global__ void convert_kernel(const float* __restrict__ in,
                               __half* __restrict__ out, int n)
{
    int i = (blockIdx.x * blockDim.x + threadIdx.x) * 4;
    if (i >= n) return;
    float4 v = *(const float4*)(in + i);
    *(__half2*)(out + i)     = __floats2half2_rn(v.x, v.y);
    *(__half2*)(out + i + 2) = __floats2half2_rn(v.z, v.w);
}

// ---------------------------------------------------------------------------
// fused transpose of all 4 weight matrices: w[K,N] -> wT[N,K] single fp16
// ---------------------------------------------------------------------------
__global__ void transpose4(const float* __restrict__ wq, const float* __restrict__ wk,
                           const float* __restrict__ wv, const float* __restrict__ wo)
{
    __shared__ float tile[32][33];
    const float* w;
    __half* oT;
    switch (blockIdx.z) {
        case 0:  w = wq; oT = g_wqT; break;
        case 1:  w = wk; oT = g_wkT; break;
        case 2:  w = wv; oT = g_wvT; break;
        default: w = wo; oT = g_woT; break;
    }
    int n = blockIdx.x * 32 + threadIdx.x;
    int k0 = blockIdx.y * 32;
#pragma unroll
    for (int j = 0; j < 32; j += 8)
        tile[threadIdx.y + j][threadIdx.x] = w[(k0 + threadIdx.y + j) * E_DIM + n];
    __syncthreads();
#pragma unroll
    for (int j = 0; j < 32; j += 8) {
        int orow = blockIdx.x * 32 + threadIdx.y + j;
        int ocol = k0 + threadIdx.x;
        oT[orow * E_DIM + ocol] = __float2half(tile[threadIdx.x][threadIdx.y + j]);
    }
}

// ---------------------------------------------------------------------------
// HMMA fp16 GEMM — single-term A and B. CTA 256x128, 512 threads
// (16 warps 4Mx4N), K-chunk 64, cp.async double buffer.
// mode 0: fp32 row-major out[M,2048] (A = g_att, B = woT)
// mode 3: fused QKV — blockIdx.x = which*16 + nb:
//         which 0: Q (RoPE, 2-term fp16 out), 1: K (RoPE, single), 2: V (single)
// ---------------------------------------------------------------------------
#define ROW_B 144
#define A_TILE_B (256 * ROW_B)       // 36864
#define B_TILE_B (128 * ROW_B)       // 18432
#define STAGE_B (A_TILE_B + B_TILE_B)  // 55296
#define EPI_B (256 * 132 * 4)        // 135168: fp32 [256][132] epilogue tile
// dynamic smem must cover BOTH the staged mainloop and the epilogue reuse
#define GEMM_SMEM (EPI_B > 2 * STAGE_B ? EPI_B : 2 * STAGE_B)   // 135168

__global__ __launch_bounds__(512, 1)
void gemm_mma(const __half* __restrict__ As, const __half* __restrict__ Bs,
              float* __restrict__ outf, const float* __restrict__ rope, int mode)
{
    extern __shared__ char smem[];
    const uint32_t smem_base = smem_u32(smem);
    const int tid = threadIdx.x;
    const int wid = tid >> 5;
    const int lane = tid & 31;
    const int m0 = blockIdx.y * 256;
    const int wM = wid >> 2;         // 0..3
    const int wN = wid & 3;          // 0..3

    const __half* b_p;
    int n0, hsel, which = -1;
    if (mode == 3) {
        which = blockIdx.x >> 4;
        int nb = blockIdx.x & 15;
        n0 = nb * 128; hsel = nb;
        b_p = (which == 0) ? g_wqT : (which == 1) ? g_wkT : g_wvT;
    } else {
        n0 = blockIdx.x * 128; hsel = blockIdx.x;
        b_p = Bs;
    }

    const char* srcA = (const char*)(As + (size_t)m0 * E_DIM);
    const char* srcB = (const char*)(b_p + (size_t)n0 * E_DIM);

    auto issue_chunk = [&](int c, int p) {
        uint32_t sb = smem_base + p * STAGE_B;
        const int kb = c * 128;   // byte offset of k-chunk in a 4096B row
#pragma unroll
        for (int i = 0; i < 4; i++) {
            int idx = tid + i * 512;
            int row = idx >> 3, c16 = idx & 7;
            uint32_t d = row * ROW_B + c16 * 16;
            CP_ASYNC16(sb + d, srcA + (size_t)row * 4096 + kb + c16 * 16);
        }
#pragma unroll
        for (int i = 0; i < 2; i++) {
            int idx = tid + i * 512;
            int row = idx >> 3, c16 = idx & 7;
            uint32_t d = row * ROW_B + c16 * 16;
            CP_ASYNC16(sb + A_TILE_B + d, srcB + (size_t)row * 4096 + kb + c16 * 16);
        }
    };

    float acc[4][4][4];
#pragma unroll
    for (int mt = 0; mt < 4; mt++)
#pragma unroll
        for (int nt = 0; nt < 4; nt++)
#pragma unroll
            for (int e = 0; e < 4; e++) acc[mt][nt][e] = 0.0f;

    const int a_row = (lane & 15);
    const int a_kb = (lane >> 4) * 16;
    const int b_nrow = (lane & 7) | ((lane & 16) >> 1);
    const int b_kb = (lane & 8) ? 16 : 0;

    issue_chunk(0, 0);
    CP_COMMIT();

    for (int c = 0; c < 32; c++) {
        if (c + 1 < 32) {
            issue_chunk(c + 1, (c + 1) & 1);
            CP_COMMIT();
            CP_WAIT1();
        } else {
            CP_WAIT0();
        }
        __syncthreads();

        uint32_t sb = smem_base + (c & 1) * STAGE_B;
        uint32_t aA = sb + (wM * 64 + a_row) * ROW_B + a_kb;
        uint32_t bB = sb + A_TILE_B + (wN * 32 + b_nrow) * ROW_B + b_kb;

#pragma unroll
        for (int ks = 0; ks < 4; ks++) {
            uint32_t a[4][4], b[4][2];
#pragma unroll
            for (int mt = 0; mt < 4; mt++) {
                LDSM4(a[mt][0], a[mt][1], a[mt][2], a[mt][3],
                      aA + mt * (16 * ROW_B) + ks * 32);
            }
#pragma unroll
            for (int bt = 0; bt < 2; bt++) {
                LDSM4(b[bt * 2][0], b[bt * 2][1], b[bt * 2 + 1][0], b[bt * 2 + 1][1],
                      bB + bt * (16 * ROW_B) + ks * 32);
            }
#pragma unroll
            for (int mt = 0; mt < 4; mt++)
#pragma unroll
                for (int nt = 0; nt < 4; nt++)
                    MMA16816(acc[mt][nt], a[mt], b[nt]);
        }
        __syncthreads();
    }

    // epilogue through smem so RoPE pairs d/d+64 are thread-local
    float* csm = (float*)smem;     // [256][132] = 135168 B (covered by GEMM_SMEM)
    const int g = lane >> 2;
    const int tg = lane & 3;
#pragma unroll
    for (int mt = 0; mt < 4; mt++)
#pragma unroll
        for (int nt = 0; nt < 4; nt++) {
            int r = wM * 64 + mt * 16 + g;
            int col = wN * 32 + nt * 8 + tg * 2;
            csm[r * 132 + col]           = acc[mt][nt][0];
            csm[r * 132 + col + 1]       = acc[mt][nt][1];
            csm[(r + 8) * 132 + col]     = acc[mt][nt][2];
            csm[(r + 8) * 132 + col + 1] = acc[mt][nt][3];
        }
    __syncthreads();

#pragma unroll 4
    for (int it = 0; it < 32; it++) {
        int idx = tid + it * 512;          // 0..16383
        int row = idx >> 6;                // 0..255
        int d = idx & 63;
        float lo = csm[row * 132 + d];
        float hi = csm[row * 132 + d + 64];
        int s = m0 + row;
        if (mode == 0) {
            float* orow = outf + (size_t)s * E_DIM + n0;
            orow[d] = lo;
            orow[d + 64] = hi;
        } else {
            if (which <= 1) {              // RoPE for Q and K
                float ang = rope[s * (D_HEAD / 2) + d];
                float sn, cs;
                __sincosf(ang, &sn, &cs);
                float nlo = lo * cs - hi * sn;
                float nhi = hi * cs + lo * sn;
                lo = nlo; hi = nhi;
            }
            size_t base = ((size_t)hsel * S_DIM + s) * D_HEAD;
            if (which == 0) {              // Q: 2-term (protects logits)
                __half hl = __float2half(lo);
                __half hh = __float2half(hi);
                g_qh[base + d]      = hl;
                g_qh[base + d + 64] = hh;
                g_ql[base + d]      = __float2half(lo - __half2float(hl));
                g_ql[base + d + 64] = __float2half(hi - __half2float(hh));
            } else if (which == 1) {       // K: single fp16
                g_k16[base + d]      = __float2half(lo);
                g_k16[base + d + 64] = __float2half(hi);
            } else {                       // V: single fp16
                g_v16[base + d]      = __float2half(lo);
                g_v16[base + d + 64] = __float2half(hi);
            }
        }
    }
}

// ---------------------------------------------------------------------------
// Block-sparse attention, fp16 mma.sync: Q 2-term, K/V single, P 2-term.
// CTA per (q-tile, head); fully-masked anchor tiles skipped (exact).
// smem: Qh, Ql, K, V  (4 x 32KB, 256B swizzled rows)
// ---------------------------------------------------------------------------
#define NEG_BIG (-1e10f)
#define ATT_TILE 32768
#define ATT_SMEM (4 * ATT_TILE)   // 131072

__global__ __launch_bounds__(256, 1)
void attn_mma(const int* __restrict__ anchors, int kanch)
{
    extern __shared__ char smn[];
    __shared__ int s_tiles[16];
    __shared__ int s_cnt;
    const uint32_t base = smem_u32(smn);
    const uint32_t Qh = base,              Ql = base + ATT_TILE;
    const uint32_t Kb = base + 2*ATT_TILE, Vb = base + 3*ATT_TILE;

    const int t = blockIdx.x, h = blockIdx.y;
    const int tid = threadIdx.x;
    const int w = tid >> 5, lane = tid & 31;
    const int g = lane >> 2, tq = lane & 3;
    const float scale = 0.088388347648318447f;

    // build filtered tile list: anchors <= t (duplicates kept), then local t
    const int abase = (h * T_NUM + t) * kanch;
    if (tid == 0) {
        int n = 0;
        for (int i = 0; i < kanch; i++) {
            int a = anchors[abase + i];
            if (a <= t) s_tiles[n++] = a;
        }
        s_tiles[n++] = t;
        s_cnt = n;
    }
    __syncthreads();
    const int cnt = s_cnt;
    int tile = s_tiles[0];

    auto load_tile = [&](uint32_t dst, const __half* src, int tl) {
        const char* p = (const char*)(src + ((size_t)h * S_DIM + (size_t)tl * 128) * D_HEAD);
        for (int i = tid; i < 2048; i += 256) {
            int row = i >> 4, c16 = i & 15;
            uint32_t off = row * 256 + ((c16 ^ (row & 7)) << 4);
            CP_ASYNC16(dst + off, p + (size_t)row * 256 + c16 * 16);
        }
    };

    // group0: Q(h,l) + K0 ; group1: V0
    load_tile(Qh, g_qh, t);
    load_tile(Ql, g_ql, t);
    load_tile(Kb, g_k16, tile);
    CP_COMMIT();
    load_tile(Vb, g_v16, tile);
    CP_COMMIT();

    float o[16][4];
#pragma unroll
    for (int j = 0; j < 16; j++)
#pragma unroll
        for (int e = 0; e < 4; e++) o[j][e] = 0.0f;
    float m0 = -1e30f, m1 = -1e30f, l0 = 0.0f, l1 = 0.0f;

    const int wrow = w * 16;
    const int arow = wrow + (lane & 15);
    const int asw = arow & 7;
    const int ahc = lane >> 4;
    const int bnr = (lane & 7) | ((lane & 16) >> 1);
    const int bhc = (lane & 8) >> 3;
    const int vrl = lane & 15;
    const int vhc = lane >> 4;

    for (int it = 0; it < cnt; it++) {
        const bool have_next = (it + 1 < cnt);
        const int nx = have_next ? s_tiles[it + 1] : 0;

        CP_WAIT1();          // K_it (and Q on it==0) ready
        __syncthreads();

        // ---- S = Q K^T (Qh + Ql terms) ----
        float s[16][4];
#pragma unroll
        for (int j = 0; j < 16; j++)
#pragma unroll
            for (int e = 0; e < 4; e++) s[j][e] = 0.0f;

#pragma unroll
        for (int ks = 0; ks < 8; ks++) {
            uint32_t qh4[4], ql4[4];
            uint32_t aoff = arow * 256 + (((ks * 2 + ahc) ^ asw) << 4);
            LDSM4(qh4[0], qh4[1], qh4[2], qh4[3], Qh + aoff);
            LDSM4(ql4[0], ql4[1], ql4[2], ql4[3], Ql + aoff);
#pragma unroll
            for (int nb = 0; nb < 8; nb++) {
                int br = nb * 16 + bnr;
                uint32_t boff = br * 256 + (((ks * 2 + bhc) ^ (br & 7)) << 4);
                uint32_t k4[4];
                LDSM4(k4[0], k4[1], k4[2], k4[3], Kb + boff);
                uint32_t b0[2] = {k4[0], k4[1]}, b1[2] = {k4[2], k4[3]};
                MMA16816(s[2 * nb],     qh4, b0);
                MMA16816(s[2 * nb],     ql4, b0);
                MMA16816(s[2 * nb + 1], qh4, b1);
                MMA16816(s[2 * nb + 1], ql4, b1);
            }
        }
        __syncthreads();                 // all warps done reading K
        if (have_next) load_tile(Kb, g_k16, nx);
        CP_COMMIT();

        // ---- mask + online softmax (quad shuffles only) ----
        const int qp0 = t * 128 + wrow + g;
        const int qp1 = qp0 + 8;
        const int kb = tile * 128 + 2 * tq;
        float mx0 = -1e30f, mx1 = -1e30f;
#pragma unroll
        for (int j = 0; j < 16; j++) {
            int kc = kb + 8 * j;
            s[j][0] = (kc     > qp0) ? NEG_BIG : s[j][0] * scale;
            s[j][1] = (kc + 1 > qp0) ? NEG_BIG : s[j][1] * scale;
            s[j][2] = (kc     > qp1) ? NEG_BIG : s[j][2] * scale;
            s[j][3] = (kc + 1 > qp1) ? NEG_BIG : s[j][3] * scale;
            mx0 = fmaxf(mx0, fmaxf(s[j][0], s[j][1]));
            mx1 = fmaxf(mx1, fmaxf(s[j][2], s[j][3]));
        }
        mx0 = fmaxf(mx0, __shfl_xor_sync(0xffffffffu, mx0, 1));
        mx0 = fmaxf(mx0, __shfl_xor_sync(0xffffffffu, mx0, 2));
        mx1 = fmaxf(mx1, __shfl_xor_sync(0xffffffffu, mx1, 1));
        mx1 = fmaxf(mx1, __shfl_xor_sync(0xffffffffu, mx1, 2));
        const float mn0 = fmaxf(m0, mx0), mn1 = fmaxf(m1, mx1);
        const float f0 = __expf(m0 - mn0), f1 = __expf(m1 - mn1);
        float ls0 = 0.0f, ls1 = 0.0f;
#pragma unroll
        for (int j = 0; j < 16; j++) {
            s[j][0] = __expf(s[j][0] - mn0);
            s[j][1] = __expf(s[j][1] - mn0);
            s[j][2] = __expf(s[j][2] - mn1);
            s[j][3] = __expf(s[j][3] - mn1);
            ls0 += s[j][0] + s[j][1];
            ls1 += s[j][2] + s[j][3];
        }
        ls0 += __shfl_xor_sync(0xffffffffu, ls0, 1);
        ls0 += __shfl_xor_sync(0xffffffffu, ls0, 2);
        ls1 += __shfl_xor_sync(0xffffffffu, ls1, 1);
        ls1 += __shfl_xor_sync(0xffffffffu, ls1, 2);
        l0 = l0 * f0 + ls0; l1 = l1 * f1 + ls1;
        m0 = mn0; m1 = mn1;
#pragma unroll
        for (int j = 0; j < 16; j++) {
            o[j][0] *= f0; o[j][1] *= f0;
            o[j][2] *= f1; o[j][3] *= f1;
        }

        CP_WAIT1();          // V_it ready
        __syncthreads();

        // ---- O += P V (Ph + Pl terms), P packed from S fragments ----
#pragma unroll
        for (int ks = 0; ks < 8; ks++) {
            uint32_t ph[4], pl[4];
            ph[0] = pack_h2(s[2 * ks][0], s[2 * ks][1]);
            ph[1] = pack_h2(s[2 * ks][2], s[2 * ks][3]);
            ph[2] = pack_h2(s[2 * ks + 1][0], s[2 * ks + 1][1]);
            ph[3] = pack_h2(s[2 * ks + 1][2], s[2 * ks + 1][3]);
            pl[0] = pack_h2_res(s[2 * ks][0], s[2 * ks][1], ph[0]);
            pl[1] = pack_h2_res(s[2 * ks][2], s[2 * ks][3], ph[1]);
            pl[2] = pack_h2_res(s[2 * ks + 1][0], s[2 * ks + 1][1], ph[2]);
            pl[3] = pack_h2_res(s[2 * ks + 1][2], s[2 * ks + 1][3], ph[3]);
            int vr = ks * 16 + vrl;
#pragma unroll
            for (int dd = 0; dd < 8; dd++) {
                uint32_t voff = vr * 256 + (((dd * 2 + vhc) ^ (vr & 7)) << 4);
                uint32_t v4[4];
                LDSM4T(v4[0], v4[1], v4[2], v4[3], Vb + voff);
                uint32_t b0[2] = {v4[0], v4[1]}, b1[2] = {v4[2], v4[3]};
                MMA16816(o[2 * dd],     ph, b0);
                MMA16816(o[2 * dd],     pl, b0);
                MMA16816(o[2 * dd + 1], ph, b1);
                MMA16816(o[2 * dd + 1], pl, b1);
            }
        }
        __syncthreads();                 // all warps done reading V
        if (have_next) load_tile(Vb, g_v16, nx);
        CP_COMMIT();

        tile = nx;
    }

    // ---- epilogue: normalize, single fp16 att to [S, H*D] ----
    const float i0 = 1.0f / l0, i1 = 1.0f / l1;
    const int s0 = t * 128 + wrow + g, s1 = s0 + 8;
#pragma unroll
    for (int j = 0; j < 16; j++) {
        int col = h * D_HEAD + 8 * j + 2 * tq;
        *(uint32_t*)(g_att + (size_t)s0 * E_DIM + col) = pack_h2(o[j][0] * i0, o[j][1] * i0);
        *(uint32_t*)(g_att + (size_t)s1 * E_DIM + col) = pack_h2(o[j][2] * i1, o[j][3] * i1);
    }
}

// ---------------------------------------------------------------------------
extern "C" void kernel_launch(void* const* d_in, const int* in_sizes, int n_in,
                              void* d_out, int out_size)
{
    const float* x    = (const float*)d_in[0];
    const float* wq   = (const float*)d_in[1];
    const float* wk   = (const float*)d_in[2];
    const float* wv   = (const float*)d_in[3];
    const float* wo   = (const float*)d_in[4];
    const float* rope = (const float*)d_in[5];
    const int* anchors = (const int*)d_in[6];
    float* out = (float*)d_out;

    const int kanch = in_sizes[6] / (H_NUM * T_NUM);  // 8

    __half *x16, *woT, *att;
    cudaGetSymbolAddress((void**)&x16, g_x16);
    cudaGetSymbolAddress((void**)&woT, g_woT);
    cudaGetSymbolAddress((void**)&att, g_att);

    cudaFuncSetAttribute(gemm_mma, cudaFuncAttributeMaxDynamicSharedMemorySize, GEMM_SMEM);
    cudaFuncSetAttribute(attn_mma, cudaFuncAttributeMaxDynamicSharedMemorySize, ATT_SMEM);

    // 1. convert x -> fp16
    convert_kernel<<<(S_DIM * E_DIM / 4 + 255) / 256, 256>>>(x, x16, S_DIM * E_DIM);

    // 2. fused transpose of all weights (single fp16)
    dim3 tgrid(E_DIM / 32, E_DIM / 32, 4), tblk(32, 8);
    transpose4<<<tgrid, tblk>>>(wq, wk, wv, wo);

    // 3. fused QKV projection (RoPE inside), head-major fp16
    dim3 qkvgrid(48, S_DIM / 256);  // (48, 16)
    gemm_mma<<<qkvgrid, 512, GEMM_SMEM>>>(x16, nullptr, nullptr, rope, 3);

    // 4. block-sparse attention (skips fully-masked tiles)
    dim3 agrid(T_NUM, H_NUM);
    attn_mma<<<agrid, 256, ATT_SMEM>>>(anchors, kanch);

    // 5. out projection -> d_out   (5th launch: ncu profiles this one)
    dim3 ogrid(E_DIM / 128, S_DIM / 256);  // (16, 16)
    gemm_mma<<<ogrid, 512, GEMM_SMEM>>>(att, woT, out, nullptr, 0);
}

// round 10
// speedup vs baseline: 7.1116x; 1.0613x over previous
#include <cuda_runtime.h>
#include <cuda_fp16.h>
#include <math.h>
#include <stdint.h>

#define S_DIM 4096
#define E_DIM 2048
#define H_NUM 16
#define D_HEAD 128
#define T_NUM 32

// ---------------------------------------------------------------------------
// Scratch (__device__ globals; allocation-free rule) — single fp16 pipeline
// ---------------------------------------------------------------------------
__device__ __half g_x16[S_DIM * E_DIM];
__device__ __half g_wqT[E_DIM * E_DIM];
__device__ __half g_wkT[E_DIM * E_DIM];
__device__ __half g_wvT[E_DIM * E_DIM];
__device__ __half g_woT[E_DIM * E_DIM];
__device__ __half g_q16[H_NUM * S_DIM * D_HEAD];
__device__ __half g_k16[H_NUM * S_DIM * D_HEAD];
__device__ __half g_v16[H_NUM * S_DIM * D_HEAD];
__device__ __half g_att[S_DIM * E_DIM];

// ---------------------------------------------------------------------------
// base-ISA PTX helpers (compute_103 virtual arch: no tcgen05/TMA)
// ---------------------------------------------------------------------------
__device__ __forceinline__ uint32_t smem_u32(const void* p) {
    uint32_t a;
    asm("{ .reg .u64 t; cvta.to.shared.u64 t, %1; cvt.u32.u64 %0, t; }" : "=r"(a) : "l"(p));
    return a;
}

#define CP_ASYNC16(dst, src) \
    asm volatile("cp.async.cg.shared.global [%0], [%1], 16;" :: "r"(dst), "l"(src))
#define CP_COMMIT() asm volatile("cp.async.commit_group;" ::: "memory")
#define CP_WAIT1() asm volatile("cp.async.wait_group 1;" ::: "memory")
#define CP_WAIT0() asm volatile("cp.async.wait_group 0;" ::: "memory")

#define LDSM4(r0, r1, r2, r3, addr) \
    asm volatile("ldmatrix.sync.aligned.m8n8.x4.shared.b16 {%0,%1,%2,%3}, [%4];" \
        : "=r"(r0), "=r"(r1), "=r"(r2), "=r"(r3) : "r"(addr))
#define LDSM4T(r0, r1, r2, r3, addr) \
    asm volatile("ldmatrix.sync.aligned.m8n8.x4.trans.shared.b16 {%0,%1,%2,%3}, [%4];" \
        : "=r"(r0), "=r"(r1), "=r"(r2), "=r"(r3) : "r"(addr))

#define MMA16816(d, a, b) \
    asm volatile("mma.sync.aligned.m16n8k16.row.col.f32.f16.f16.f32 " \
        "{%0,%1,%2,%3}, {%4,%5,%6,%7}, {%8,%9}, {%0,%1,%2,%3};" \
        : "+f"((d)[0]), "+f"((d)[1]), "+f"((d)[2]), "+f"((d)[3]) \
        : "r"((a)[0]), "r"((a)[1]), "r"((a)[2]), "r"((a)[3]), \
          "r"((b)[0]), "r"((b)[1]))

__device__ __forceinline__ uint32_t pack_h2(float a, float b) {
    __half2 v = __floats2half2_rn(a, b);
    return *(uint32_t*)&v;
}

// ---------------------------------------------------------------------------
// fp32 -> fp16 convert (x)
// ---------------------------------------------------------------------------
__global__ void convert_kernel(const float* __restrict__ in,
                               __half* __restrict__ out, int n)
{
    int i = (blockIdx.x * blockDim.x + threadIdx.x) * 4;
    if (i >= n) return;
    float4 v = *(const float4*)(in + i);
    *(__half2*)(out + i)     = __floats2half2_rn(v.x, v.y);
    *(__half2*)(out + i + 2) = __floats2half2_rn(v.z, v.w);
}

// ---------------------------------------------------------------------------
// fused transpose of all 4 weight matrices: w[K,N] -> wT[N,K] single fp16
// ---------------------------------------------------------------------------
__global__ void transpose4(const float* __restrict__ wq, const float* __restrict__ wk,
                           const float* __restrict__ wv, const float* __restrict__ wo)
{
    __shared__ float tile[32][33];
    const float* w;
    __half* oT;
    switch (blockIdx.z) {
        case 0:  w = wq; oT = g_wqT; break;
        case 1:  w = wk; oT = g_wkT; break;
        case 2:  w = wv; oT = g_wvT; break;
        default: w = wo; oT = g_woT; break;
    }
    int n = blockIdx.x * 32 + threadIdx.x;
    int k0 = blockIdx.y * 32;
#pragma unroll
    for (int j = 0; j < 32; j += 8)
        tile[threadIdx.y + j][threadIdx.x] = w[(k0 + threadIdx.y + j) * E_DIM + n];
    __syncthreads();
#pragma unroll
    for (int j = 0; j < 32; j += 8) {
        int orow = blockIdx.x * 32 + threadIdx.y + j;
        int ocol = k0 + threadIdx.x;
        oT[orow * E_DIM + ocol] = __float2half(tile[threadIdx.x][threadIdx.y + j]);
    }
}

// ---------------------------------------------------------------------------
// HMMA fp16 GEMM — single-term. CTA 256x128, 512 threads (16 warps 4Mx4N),
// K-chunk 64, cp.async double buffer.
// mode 0: fp32 row-major out[M,2048] (A = g_att, B = woT)
// mode 3: fused QKV — blockIdx.x = which*16 + nb; RoPE for Q,K; fp16 outs
// ---------------------------------------------------------------------------
#define ROW_B 144
#define A_TILE_B (256 * ROW_B)       // 36864
#define B_TILE_B (128 * ROW_B)       // 18432
#define STAGE_B (A_TILE_B + B_TILE_B)  // 55296
#define EPI_B (256 * 132 * 4)        // 135168 fp32 epilogue tile
#define GEMM_SMEM (EPI_B > 2 * STAGE_B ? EPI_B : 2 * STAGE_B)   // 135168

__global__ __launch_bounds__(512, 1)
void gemm_mma(const __half* __restrict__ As, const __half* __restrict__ Bs,
              float* __restrict__ outf, const float* __restrict__ rope, int mode)
{
    extern __shared__ char smem[];
    const uint32_t smem_base = smem_u32(smem);
    const int tid = threadIdx.x;
    const int wid = tid >> 5;
    const int lane = tid & 31;
    const int m0 = blockIdx.y * 256;
    const int wM = wid >> 2;         // 0..3
    const int wN = wid & 3;          // 0..3

    const __half* b_p;
    int n0, hsel, which = -1;
    if (mode == 3) {
        which = blockIdx.x >> 4;
        int nb = blockIdx.x & 15;
        n0 = nb * 128; hsel = nb;
        b_p = (which == 0) ? g_wqT : (which == 1) ? g_wkT : g_wvT;
    } else {
        n0 = blockIdx.x * 128; hsel = blockIdx.x;
        b_p = Bs;
    }

    const char* srcA = (const char*)(As + (size_t)m0 * E_DIM);
    const char* srcB = (const char*)(b_p + (size_t)n0 * E_DIM);

    auto issue_chunk = [&](int c, int p) {
        uint32_t sb = smem_base + p * STAGE_B;
        const int kb = c * 128;
#pragma unroll
        for (int i = 0; i < 4; i++) {
            int idx = tid + i * 512;
            int row = idx >> 3, c16 = idx & 7;
            uint32_t d = row * ROW_B + c16 * 16;
            CP_ASYNC16(sb + d, srcA + (size_t)row * 4096 + kb + c16 * 16);
        }
#pragma unroll
        for (int i = 0; i < 2; i++) {
            int idx = tid + i * 512;
            int row = idx >> 3, c16 = idx & 7;
            uint32_t d = row * ROW_B + c16 * 16;
            CP_ASYNC16(sb + A_TILE_B + d, srcB + (size_t)row * 4096 + kb + c16 * 16);
        }
    };

    float acc[4][4][4];
#pragma unroll
    for (int mt = 0; mt < 4; mt++)
#pragma unroll
        for (int nt = 0; nt < 4; nt++)
#pragma unroll
            for (int e = 0; e < 4; e++) acc[mt][nt][e] = 0.0f;

    const int a_row = (lane & 15);
    const int a_kb = (lane >> 4) * 16;
    const int b_nrow = (lane & 7) | ((lane & 16) >> 1);
    const int b_kb = (lane & 8) ? 16 : 0;

    issue_chunk(0, 0);
    CP_COMMIT();

    for (int c = 0; c < 32; c++) {
        if (c + 1 < 32) {
            issue_chunk(c + 1, (c + 1) & 1);
            CP_COMMIT();
            CP_WAIT1();
        } else {
            CP_WAIT0();
        }
        __syncthreads();

        uint32_t sb = smem_base + (c & 1) * STAGE_B;
        uint32_t aA = sb + (wM * 64 + a_row) * ROW_B + a_kb;
        uint32_t bB = sb + A_TILE_B + (wN * 32 + b_nrow) * ROW_B + b_kb;

#pragma unroll
        for (int ks = 0; ks < 4; ks++) {
            uint32_t a[4][4], b[4][2];
#pragma unroll
            for (int mt = 0; mt < 4; mt++) {
                LDSM4(a[mt][0], a[mt][1], a[mt][2], a[mt][3],
                      aA + mt * (16 * ROW_B) + ks * 32);
            }
#pragma unroll
            for (int bt = 0; bt < 2; bt++) {
                LDSM4(b[bt * 2][0], b[bt * 2][1], b[bt * 2 + 1][0], b[bt * 2 + 1][1],
                      bB + bt * (16 * ROW_B) + ks * 32);
            }
#pragma unroll
            for (int mt = 0; mt < 4; mt++)
#pragma unroll
                for (int nt = 0; nt < 4; nt++)
                    MMA16816(acc[mt][nt], a[mt], b[nt]);
        }
        __syncthreads();
    }

    // epilogue through smem so RoPE pairs d/d+64 are thread-local
    float* csm = (float*)smem;     // [256][132]
    const int g = lane >> 2;
    const int tg = lane & 3;
#pragma unroll
    for (int mt = 0; mt < 4; mt++)
#pragma unroll
        for (int nt = 0; nt < 4; nt++) {
            int r = wM * 64 + mt * 16 + g;
            int col = wN * 32 + nt * 8 + tg * 2;
            csm[r * 132 + col]           = acc[mt][nt][0];
            csm[r * 132 + col + 1]       = acc[mt][nt][1];
            csm[(r + 8) * 132 + col]     = acc[mt][nt][2];
            csm[(r + 8) * 132 + col + 1] = acc[mt][nt][3];
        }
    __syncthreads();

#pragma unroll 4
    for (int it = 0; it < 32; it++) {
        int idx = tid + it * 512;
        int row = idx >> 6;
        int d = idx & 63;
        float lo = csm[row * 132 + d];
        float hi = csm[row * 132 + d + 64];
        int s = m0 + row;
        if (mode == 0) {
            float* orow = outf + (size_t)s * E_DIM + n0;
            orow[d] = lo;
            orow[d + 64] = hi;
        } else {
            if (which <= 1) {              // RoPE for Q and K
                float ang = rope[s * (D_HEAD / 2) + d];
                float sn, cs;
                __sincosf(ang, &sn, &cs);
                float nlo = lo * cs - hi * sn;
                float nhi = hi * cs + lo * sn;
                lo = nlo; hi = nhi;
            }
            size_t base = ((size_t)hsel * S_DIM + s) * D_HEAD;
            __half* dst = (which == 0) ? g_q16 : (which == 1) ? g_k16 : g_v16;
            dst[base + d]      = __float2half(lo);
            dst[base + d + 64] = __float2half(hi);
        }
    }
}

// ---------------------------------------------------------------------------
// Block-sparse attention, single-term fp16 mma.sync, CTA per (q-tile, head).
// Fully-masked anchor tiles skipped (exact); inside the diagonal tile,
// fully-masked S fragments and all-zero P chunks skipped per warp (exact).
// smem: Q, K, V  (3 x 32KB, 256B swizzled rows)
// ---------------------------------------------------------------------------
#define NEG_BIG (-1e10f)
#define ATT_TILE 32768
#define ATT_SMEM (3 * ATT_TILE)   // 98304

__global__ __launch_bounds__(256, 1)
void attn_mma(const int* __restrict__ anchors, int kanch)
{
    extern __shared__ char smn[];
    __shared__ int s_tiles[16];
    __shared__ int s_cnt;
    const uint32_t base = smem_u32(smn);
    const uint32_t Qb = base;
    const uint32_t Kb = base + ATT_TILE;
    const uint32_t Vb = base + 2 * ATT_TILE;

    const int t = blockIdx.x, h = blockIdx.y;
    const int tid = threadIdx.x;
    const int w = tid >> 5, lane = tid & 31;
    const int g = lane >> 2, tq = lane & 3;
    const float scale = 0.088388347648318447f;

    // build filtered tile list: anchors <= t (duplicates kept), then local t
    const int abase = (h * T_NUM + t) * kanch;
    if (tid == 0) {
        int n = 0;
        for (int i = 0; i < kanch; i++) {
            int a = anchors[abase + i];
            if (a <= t) s_tiles[n++] = a;
        }
        s_tiles[n++] = t;
        s_cnt = n;
    }
    __syncthreads();
    const int cnt = s_cnt;
    int tile = s_tiles[0];

    auto load_tile = [&](uint32_t dst, const __half* src, int tl) {
        const char* p = (const char*)(src + ((size_t)h * S_DIM + (size_t)tl * 128) * D_HEAD);
        for (int i = tid; i < 2048; i += 256) {
            int row = i >> 4, c16 = i & 15;
            uint32_t off = row * 256 + ((c16 ^ (row & 7)) << 4);
            CP_ASYNC16(dst + off, p + (size_t)row * 256 + c16 * 16);
        }
    };

    // group0: Q + K0 ; group1: V0
    load_tile(Qb, g_q16, t);
    load_tile(Kb, g_k16, tile);
    CP_COMMIT();
    load_tile(Vb, g_v16, tile);
    CP_COMMIT();

    float o[16][4];
#pragma unroll
    for (int j = 0; j < 16; j++)
#pragma unroll
        for (int e = 0; e < 4; e++) o[j][e] = 0.0f;
    float m0 = -1e30f, m1 = -1e30f, l0 = 0.0f, l1 = 0.0f;

    const int wrow = w * 16;
    const int arow = wrow + (lane & 15);
    const int asw = arow & 7;
    const int ahc = lane >> 4;
    const int bnr = (lane & 7) | ((lane & 16) >> 1);
    const int bhc = (lane & 8) >> 3;
    const int vrl = lane & 15;
    const int vhc = lane >> 4;

    for (int it = 0; it < cnt; it++) {
        const bool have_next = (it + 1 < cnt);
        const int nx = have_next ? s_tiles[it + 1] : 0;
        const bool isdiag = (tile == t);   // causal structure inside this tile

        CP_WAIT1();          // K_it (and Q on it==0) ready
        __syncthreads();

        // ---- S = Q K^T (single term); skip fully-masked K blocks on diag ----
        float s[16][4];
#pragma unroll
        for (int j = 0; j < 16; j++)
#pragma unroll
            for (int e = 0; e < 4; e++) s[j][e] = 0.0f;

#pragma unroll
        for (int ks = 0; ks < 8; ks++) {
            uint32_t q4[4];
            uint32_t aoff = arow * 256 + (((ks * 2 + ahc) ^ asw) << 4);
            LDSM4(q4[0], q4[1], q4[2], q4[3], Qb + aoff);
#pragma unroll
            for (int nb = 0; nb < 8; nb++) {
                if (isdiag && nb > w) continue;   // keys 16nb.. all future of row 16w+15
                int br = nb * 16 + bnr;
                uint32_t boff = br * 256 + (((ks * 2 + bhc) ^ (br & 7)) << 4);
                uint32_t k4[4];
                LDSM4(k4[0], k4[1], k4[2], k4[3], Kb + boff);
                uint32_t b0[2] = {k4[0], k4[1]}, b1[2] = {k4[2], k4[3]};
                MMA16816(s[2 * nb],     q4, b0);
                MMA16816(s[2 * nb + 1], q4, b1);
            }
        }
        __syncthreads();                 // all warps done reading K
        if (have_next) load_tile(Kb, g_k16, nx);
        CP_COMMIT();

        // ---- mask + online softmax (quad shuffles only) ----
        const int qp0 = t * 128 + wrow + g;
        const int qp1 = qp0 + 8;
        const int kb = tile * 128 + 2 * tq;
        float mx0 = -1e30f, mx1 = -1e30f;
#pragma unroll
        for (int j = 0; j < 16; j++) {
            int kc = kb + 8 * j;
            s[j][0] = (kc     > qp0) ? NEG_BIG : s[j][0] * scale;
            s[j][1] = (kc + 1 > qp0) ? NEG_BIG : s[j][1] * scale;
            s[j][2] = (kc     > qp1) ? NEG_BIG : s[j][2] * scale;
            s[j][3] = (kc + 1 > qp1) ? NEG_BIG : s[j][3] * scale;
            mx0 = fmaxf(mx0, fmaxf(s[j][0], s[j][1]));
            mx1 = fmaxf(mx1, fmaxf(s[j][2], s[j][3]));
        }
        mx0 = fmaxf(mx0, __shfl_xor_sync(0xffffffffu, mx0, 1));
        mx0 = fmaxf(mx0, __shfl_xor_sync(0xffffffffu, mx0, 2));
        mx1 = fmaxf(mx1, __shfl_xor_sync(0xffffffffu, mx1, 1));
        mx1 = fmaxf(mx1, __shfl_xor_sync(0xffffffffu, mx1, 2));
        const float mn0 = fmaxf(m0, mx0), mn1 = fmaxf(m1, mx1);
        const float f0 = __expf(m0 - mn0), f1 = __expf(m1 - mn1);
        float ls0 = 0.0f, ls1 = 0.0f;
#pragma unroll
        for (int j = 0; j < 16; j++) {
            s[j][0] = __expf(s[j][0] - mn0);
            s[j][1] = __expf(s[j][1] - mn0);
            s[j][2] = __expf(s[j][2] - mn1);
            s[j][3] = __expf(s[j][3] - mn1);
            ls0 += s[j][0] + s[j][1];
            ls1 += s[j][2] + s[j][3];
        }
        ls0 += __shfl_xor_sync(0xffffffffu, ls0, 1);
        ls0 += __shfl_xor_sync(0xffffffffu, ls0, 2);
        ls1 += __shfl_xor_sync(0xffffffffu, ls1, 1);
        ls1 += __shfl_xor_sync(0xffffffffu, ls1, 2);
        l0 = l0 * f0 + ls0; l1 = l1 * f1 + ls1;
        m0 = mn0; m1 = mn1;
#pragma unroll
        for (int j = 0; j < 16; j++) {
            o[j][0] *= f0; o[j][1] *= f0;
            o[j][2] *= f1; o[j][3] *= f1;
        }

        CP_WAIT1();          // V_it ready
        __syncthreads();

        // ---- O += P V (single term); skip all-zero P chunks on diag ----
#pragma unroll
        for (int ks = 0; ks < 8; ks++) {
            if (isdiag && ks > w) continue;   // P columns 16ks.. all zero for this warp
            uint32_t ph[4];
            ph[0] = pack_h2(s[2 * ks][0], s[2 * ks][1]);
            ph[1] = pack_h2(s[2 * ks][2], s[2 * ks][3]);
            ph[2] = pack_h2(s[2 * ks + 1][0], s[2 * ks + 1][1]);
            ph[3] = pack_h2(s[2 * ks + 1][2], s[2 * ks + 1][3]);
            int vr = ks * 16 + vrl;
#pragma unroll
            for (int dd = 0; dd < 8; dd++) {
                uint32_t voff = vr * 256 + (((dd * 2 + vhc) ^ (vr & 7)) << 4);
                uint32_t v4[4];
                LDSM4T(v4[0], v4[1], v4[2], v4[3], Vb + voff);
                uint32_t b0[2] = {v4[0], v4[1]}, b1[2] = {v4[2], v4[3]};
                MMA16816(o[2 * dd],     ph, b0);
                MMA16816(o[2 * dd + 1], ph, b1);
            }
        }
        __syncthreads();                 // all warps done reading V
        if (have_next) load_tile(Vb, g_v16, nx);
        CP_COMMIT();

        tile = nx;
    }

    // ---- epilogue: normalize, fp16 att to [S, H*D] ----
    const float i0 = 1.0f / l0, i1 = 1.0f / l1;
    const int s0 = t * 128 + wrow + g, s1 = s0 + 8;
#pragma unroll
    for (int j = 0; j < 16; j++) {
        int col = h * D_HEAD + 8 * j + 2 * tq;
        *(uint32_t*)(g_att + (size_t)s0 * E_DIM + col) = pack_h2(o[j][0] * i0, o[j][1] * i0);
        *(uint32_t*)(g_att + (size_t)s1 * E_DIM + col) = pack_h2(o[j][2] * i1, o[j][3] * i1);
    }
}

// ---------------------------------------------------------------------------
extern "C" void kernel_launch(void* const* d_in, const int* in_sizes, int n_in,
                              void* d_out, int out_size)
{
    const float* x    = (const float*)d_in[0];
    const float* wq   = (const float*)d_in[1];
    const float* wk   = (const float*)d_in[2];
    const float* wv   = (const float*)d_in[3];
    const float* wo   = (const float*)d_in[4];
    const float* rope = (const float*)d_in[5];
    const int* anchors = (const int*)d_in[6];
    float* out = (float*)d_out;

    const int kanch = in_sizes[6] / (H_NUM * T_NUM);  // 8

    __half *x16, *woT, *att;
    cudaGetSymbolAddress((void**)&x16, g_x16);
    cudaGetSymbolAddress((void**)&woT, g_woT);
    cudaGetSymbolAddress((void**)&att, g_att);

    cudaFuncSetAttribute(gemm_mma, cudaFuncAttributeMaxDynamicSharedMemorySize, GEMM_SMEM);
    cudaFuncSetAttribute(attn_mma, cudaFuncAttributeMaxDynamicSharedMemorySize, ATT_SMEM);

    // 1. convert x -> fp16
    convert_kernel<<<(S_DIM * E_DIM / 4 + 255) / 256, 256>>>(x, x16, S_DIM * E_DIM);

    // 2. fused transpose of all weights (single fp16)
    dim3 tgrid(E_DIM / 32, E_DIM / 32, 4), tblk(32, 8);
    transpose4<<<tgrid, tblk>>>(wq, wk, wv, wo);

    // 3. fused QKV projection (RoPE inside), head-major fp16
    dim3 qkvgrid(48, S_DIM / 256);  // (48, 16)
    gemm_mma<<<qkvgrid, 512, GEMM_SMEM>>>(x16, nullptr, nullptr, rope, 3);

    // 4. block-sparse attention (tile-skip + intra-diagonal causal skip)
    dim3 agrid(T_NUM, H_NUM);
    attn_mma<<<agrid, 256, ATT_SMEM>>>(anchors, kanch);

    // 5. out projection -> d_out
    dim3 ogrid(E_DIM / 128, S_DIM / 256);  // (16, 16)
    gemm_mma<<<ogrid, 512, GEMM_SMEM>>>(att, woT, out, nullptr, 0);
}